// round 8
// baseline (speedup 1.0000x reference)
#include <cuda_runtime.h>
#include <cstdint>
#include <math.h>

// ---------------- problem constants ----------------
#define S_ROWS 2047          // N_PART - 1
#define SPAD   2048
#define DIM    256
#define HID    512
#define NB     16
#define NFREQ  8
#define NBLK   4
#define NHEAD  8
#define EMB_IN 35
#define CONDP  64            // padded cond width
#define AFF_OUT 49
#define POS_ELEMS (2048*3)
#define KVSPLIT 2

// ---- presplit weight buffer offsets (uint2 units) ----
#define OFF_EW0 0
#define OFF_EW1 32768
#define OFF_EW2 294912
#define OFF_WQ  425984
#define OFF_WK  688128
#define OFF_WV  950272
#define OFF_WO  1212416
#define OFF_MW0 1474560
#define OFF_MW1 1998848
#define OFF_MW2 3047424
#define OFF_AW0 3571712
#define OFF_AW1 3702784
#define OFF_AW2 3964928
#define WSPLIT_TOTAL 3997696

// gemm smem: As[2][32][36] + Bs[2][64][36] uint2
#define GEMM_SMEM ((2*32*36 + 2*64*36) * 8)
// flash smem: Ks[2][64][36] + Vs[2][64][36] uint2 (no P buffer)
#define FLASH_SMEM ((2*64*36 + 2*64*36) * 8)

// ---------------- scratch (static device memory; zero-initialized) --------
__device__ __align__(16) uint2 g_wsplit[WSPLIT_TOTAL];
__device__ float g_cond[SPAD * CONDP];
__device__ float g_a[SPAD * HID];
__device__ float g_b[SPAD * HID];
__device__ float g_h[SPAD * DIM];
__device__ float g_t[SPAD * DIM];
__device__ float g_q[SPAD * DIM];
__device__ float g_k[SPAD * DIM];
__device__ float g_v[SPAD * DIM];
__device__ float g_po[KVSPLIT][SPAD * DIM];     // flash partial outputs
__device__ float2 g_pml[KVSPLIT][SPAD * NHEAD]; // flash partial (m, l)
__device__ float g_params[SPAD * AFF_OUT];
__device__ float g_ld[S_ROWS];

// ---------------- helpers ---------------------------------------------------
__device__ __forceinline__ uint32_t f2tf32(float f) {
    uint32_t u;
    asm("cvt.rna.tf32.f32 %0, %1;" : "=r"(u) : "f"(f));
    return u;
}

__device__ __forceinline__ uint2 split_tf32(float f) {
    uint32_t hi = f2tf32(f);
    uint32_t lo = f2tf32(f - __uint_as_float(hi));
    return make_uint2(hi, lo);
}

__device__ __forceinline__ void mma_tf32(float c[4], const uint32_t a[4],
                                         const uint32_t b[2]) {
    asm volatile(
        "mma.sync.aligned.m16n8k8.row.col.f32.tf32.tf32.f32 "
        "{%0,%1,%2,%3}, {%4,%5,%6,%7}, {%8,%9}, {%0,%1,%2,%3};"
        : "+f"(c[0]), "+f"(c[1]), "+f"(c[2]), "+f"(c[3])
        : "r"(a[0]), "r"(a[1]), "r"(a[2]), "r"(a[3]), "r"(b[0]), "r"(b[1]));
}

__device__ __forceinline__ void mma3(float c[4], const uint32_t aH[4],
                                     const uint32_t aL[4], const uint32_t bH[2],
                                     const uint32_t bL[2]) {
    mma_tf32(c, aL, bH);
    mma_tf32(c, aH, bL);
    mma_tf32(c, aH, bH);
}

__device__ __forceinline__ void cp_async16(void* smem, const void* gptr) {
    uint32_t s = (uint32_t)__cvta_generic_to_shared(smem);
    asm volatile("cp.async.cg.shared.global [%0], [%1], 16;" :: "r"(s), "l"(gptr));
}
__device__ __forceinline__ void cp_commit() {
    asm volatile("cp.async.commit_group;");
}
__device__ __forceinline__ void cp_wait0() {
    asm volatile("cp.async.wait_group 0;");
}

// ---------------- weight presplit (flat grid, one launch) --------------------
__global__ void wsplit_kernel(const float* e0, const float* e1, const float* e2,
                              const float* wq, const float* wk, const float* wv,
                              const float* wo, const float* m0, const float* m1,
                              const float* m2, const float* a0, const float* a1,
                              const float* a2) {
    const int OFF[14] = {OFF_EW0,OFF_EW1,OFF_EW2,OFF_WQ,OFF_WK,OFF_WV,OFF_WO,
                         OFF_MW0,OFF_MW1,OFF_MW2,OFF_AW0,OFF_AW1,OFF_AW2,
                         WSPLIT_TOTAL};
    const int NS[13] = {512,512,256,1024,1024,1024,1024,2048,2048,1024,512,512,49};
    const int KS[13] = {35,512,512,256,256,256,256,256,512,512,256,512,512};
    const int KP[13] = {64,512,512,256,256,256,256,256,512,512,256,512,512};
    const float* srcs[13] = {e0,e1,e2,wq,wk,wv,wo,m0,m1,m2,a0,a1,a2};

    int idx = blockIdx.x * 256 + threadIdx.x;
    if (idx >= WSPLIT_TOTAL) return;
    int z = 0;
    #pragma unroll
    for (int i = 1; i < 13; i++) z += (idx >= OFF[i]) ? 1 : 0;
    int local = idx - OFF[z];
    int n = local / KP[z];
    int kk = local - n * KP[z];
    float v = (n < NS[z] && kk < KS[z]) ? srcs[z][(size_t)n * KS[z] + kk] : 0.f;
    g_wsplit[idx] = split_tf32(v);
}

// ---------------- circular features (padded cond) ----------------------------
__global__ void embed_kernel(const float* __restrict__ pos,
                             const float* __restrict__ scale,
                             const float* __restrict__ press,
                             const float* __restrict__ temp,
                             float* __restrict__ cond) {
    int s = blockIdx.x * blockDim.x + threadIdx.x;
    if (s >= SPAD) return;
    float* c = cond + s * CONDP;
    if (s >= S_ROWS) {
        #pragma unroll
        for (int i = 0; i < CONDP; i++) c[i] = 0.f;
        return;
    }
    const float TWO_PI = 6.28318530717958647692f;
    float xs[2];
    xs[0] = pos[(s + 1) * 3 + 0];
    xs[1] = pos[(s + 1) * 3 + 1];
    #pragma unroll
    for (int cc = 0; cc < 2; cc++) {
        float x = xs[cc];
        #pragma unroll
        for (int f = 1; f <= NFREQ; f++) {
            float sn, cs;
            sincosf(TWO_PI * (float)f * x, &sn, &cs);
            c[cc * 16 + (f - 1)]     = cs;
            c[cc * 16 + 8 + (f - 1)] = sn;
        }
    }
    c[32] = *scale;
    c[33] = *temp;
    c[34] = *press;
    #pragma unroll
    for (int i = EMB_IN; i < CONDP; i++) c[i] = 0.f;
}

// ---------------- GEMM v6: presplit-B cp.async, 1 barrier/stage --------------
// C[2047 x Nstore] = A[2048 x lda] @ Bsplit^T (+bias)(+res)(relu)
// block tile 32x64, 256 thr (8 warps, 2m x 4n), warp tile 16x16.
#define GAS(b,r,c) sm[((b)*32 + (r))*36 + (c)]
#define GBS(b,r,c) sm[2304 + ((b)*64 + (r))*36 + (c)]

template <bool RELU>
__device__ __forceinline__
void gemm_core(const float* __restrict__ A, int lda,
               const uint2* __restrict__ B,
               const float* __restrict__ bias, const float* __restrict__ res,
               float* __restrict__ C, int Nstore, int Kp) {
    extern __shared__ uint2 sm[];

    const int tid  = threadIdx.x;
    const int lane = tid & 31;
    const int wid  = tid >> 5;
    const int warp_m = wid >> 2;
    const int warp_n = wid & 3;
    const int g   = lane >> 2;
    const int tig = lane & 3;

    const int m0 = blockIdx.y * 32;
    const int n0 = blockIdx.x * 64;

    const int aRow = tid >> 3;          // 0..31
    const int aCol = (tid & 7) * 4;
    // B cp.async mapping: 4 x 16B per thread per stage
    int bRow[4], bCol[4];
    #pragma unroll
    for (int i = 0; i < 4; i++) {
        int cc = i * 256 + tid;         // 0..1023
        bRow[i] = cc >> 4;              // 0..63
        bCol[i] = (cc & 15) * 2;        // 0,2,...,30 (uint2 cols)
    }
    const int stages = Kp >> 5;

    float av[4];

    // ---- prologue: issue B stage 0, load A stage 0 ----
    #pragma unroll
    for (int i = 0; i < 4; i++)
        cp_async16(&GBS(0, bRow[i], bCol[i]),
                   B + (size_t)(n0 + bRow[i]) * Kp + bCol[i]);
    cp_commit();
    {
        float4 a4 = *(const float4*)(A + (size_t)(m0 + aRow) * lda + aCol);
        av[0] = a4.x; av[1] = a4.y; av[2] = a4.z; av[3] = a4.w;
    }

    float acc[2][4];
    #pragma unroll
    for (int nt = 0; nt < 2; nt++)
        #pragma unroll
        for (int i = 0; i < 4; i++) acc[nt][i] = 0.f;

    for (int s = 0; s < stages; s++) {
        const int cur = s & 1;

        // commit A_s into smem[cur]
        #pragma unroll
        for (int j = 0; j < 4; j++)
            GAS(cur, aRow, aCol + j) = split_tf32(av[j]);

        cp_wait0();          // B_cur landed
        __syncthreads();     // everyone's A_cur + B_cur visible

        // issue next stage (other buffer; prior readers are past the barrier)
        if (s + 1 < stages) {
            const int k0 = (s + 1) * 32;
            const int nb = (s + 1) & 1;
            #pragma unroll
            for (int i = 0; i < 4; i++)
                cp_async16(&GBS(nb, bRow[i], bCol[i]),
                           B + (size_t)(n0 + bRow[i]) * Kp + k0 + bCol[i]);
            cp_commit();
            float4 a4 = *(const float4*)(A + (size_t)(m0 + aRow) * lda + k0 + aCol);
            av[0] = a4.x; av[1] = a4.y; av[2] = a4.z; av[3] = a4.w;
        }

        // mma over current buffer
        #pragma unroll
        for (int k8 = 0; k8 < 4; k8++) {
            const int kk = k8 * 8;
            const int r = warp_m * 16 + g;
            uint2 p0 = GAS(cur, r,     kk + tig);
            uint2 p1 = GAS(cur, r + 8, kk + tig);
            uint2 p2 = GAS(cur, r,     kk + tig + 4);
            uint2 p3 = GAS(cur, r + 8, kk + tig + 4);
            uint32_t aH[4] = {p0.x, p1.x, p2.x, p3.x};
            uint32_t aL[4] = {p0.y, p1.y, p2.y, p3.y};
            #pragma unroll
            for (int nt = 0; nt < 2; nt++) {
                int ci = warp_n * 16 + nt * 8 + g;
                uint2 q0 = GBS(cur, ci, kk + tig);
                uint2 q1 = GBS(cur, ci, kk + tig + 4);
                uint32_t bH[2] = {q0.x, q1.x};
                uint32_t bL[2] = {q0.y, q1.y};
                mma3(acc[nt], aH, aL, bH, bL);
            }
        }
        // next iteration's A-split writes the other buffer; safe without a
        // second barrier (see hazard analysis in commit message)
    }

    // epilogue
    #pragma unroll
    for (int nt = 0; nt < 2; nt++) {
        int r0 = m0 + warp_m * 16 + g;
        int cb = n0 + warp_n * 16 + nt * 8 + tig * 2;
        #pragma unroll
        for (int half = 0; half < 2; half++) {
            int r = r0 + half * 8;
            if (r >= S_ROWS) continue;
            #pragma unroll
            for (int j = 0; j < 2; j++) {
                int n = cb + j;
                if (n >= Nstore) continue;
                float v = acc[nt][half * 2 + j];
                if (bias) v += bias[n];
                if (res)  v += res[(size_t)r * Nstore + n];
                if (RELU) v = fmaxf(v, 0.f);
                C[(size_t)r * Nstore + n] = v;
            }
        }
    }
}

template <bool RELU>
__global__ __launch_bounds__(256)
void gemm_v6_kernel(const float* __restrict__ A, int lda,
                    const uint2* __restrict__ B,
                    const float* __restrict__ bias, const float* __restrict__ res,
                    float* __restrict__ C, int Nstore, int Kp) {
    gemm_core<RELU>(A, lda, B, bias, res, C, Nstore, Kp);
}

// fused q/k/v projection via blockIdx.z
__global__ __launch_bounds__(256)
void gemm_qkv_kernel(const float* __restrict__ h, int woff,
                     const float* __restrict__ bk,
                     float* __restrict__ q, float* __restrict__ k,
                     float* __restrict__ v) {
    int z = blockIdx.z;
    const uint2* B = g_wsplit + ((z == 0) ? (OFF_WQ + woff)
                                : (z == 1) ? (OFF_WK + woff) : (OFF_WV + woff));
    const float* bias = (z == 1) ? bk : nullptr;
    float* C = (z == 0) ? q : (z == 1) ? k : v;
    gemm_core<false>(h, DIM, B, bias, nullptr, C, DIM, DIM);
}

// ---------------- flash attention v5: register-P + kv-split -----------------
#define FKS(b,r,c) sm[((b)*64 + (r))*36 + (c)]
#define FVS(b,r,c) sm[4608 + ((b)*64 + (r))*36 + (c)]

__global__ __launch_bounds__(128)
void flash_mma_kernel(const float* __restrict__ q,
                      const float* __restrict__ k,
                      const float* __restrict__ v) {
    extern __shared__ uint2 sm[];

    const int S = S_ROWS, D = DIM;
    const int head = blockIdx.y;
    const int z = blockIdx.z;
    const int s0 = blockIdx.x * 64;
    const int tid = threadIdx.x;
    const int lane = tid & 31;
    const int wid = tid >> 5;
    const int g = lane >> 2;
    const int tig = lane & 3;
    const float scl = 0.17677669529663688f; // 1/sqrt(32)
    const int TPB = 32 / KVSPLIT;
    const int tbase = z * TPB;

    uint32_t aQH[4][4], aQL[4][4];
    {
        const int ra = s0 + wid * 16 + g;
        const int rb = ra + 8;
        #pragma unroll
        for (int k8 = 0; k8 < 4; k8++) {
            const int c0 = head * 32 + k8 * 8 + tig;
            uint2 p0 = split_tf32(q[(size_t)ra * D + c0] * scl);
            uint2 p1 = split_tf32(q[(size_t)rb * D + c0] * scl);
            uint2 p2 = split_tf32(q[(size_t)ra * D + c0 + 4] * scl);
            uint2 p3 = split_tf32(q[(size_t)rb * D + c0 + 4] * scl);
            aQH[k8][0] = p0.x; aQH[k8][1] = p1.x; aQH[k8][2] = p2.x; aQH[k8][3] = p3.x;
            aQL[k8][0] = p0.y; aQL[k8][1] = p1.y; aQL[k8][2] = p2.y; aQL[k8][3] = p3.y;
        }
    }

    float4 kr[4], vr[4];
    int ldR[4], ldC[4];
    #pragma unroll
    for (int i = 0; i < 4; i++) {
        int cc = i * 128 + tid;
        ldR[i] = cc >> 3;
        ldC[i] = (cc & 7) * 4;
    }

    #pragma unroll
    for (int i = 0; i < 4; i++) {
        size_t off = (size_t)(tbase * 64 + ldR[i]) * D + head * 32 + ldC[i];
        kr[i] = *(const float4*)&k[off];
        vr[i] = *(const float4*)&v[off];
    }
    #pragma unroll
    for (int i = 0; i < 4; i++) {
        FKS(0, ldR[i], ldC[i] + 0) = split_tf32(kr[i].x);
        FKS(0, ldR[i], ldC[i] + 1) = split_tf32(kr[i].y);
        FKS(0, ldR[i], ldC[i] + 2) = split_tf32(kr[i].z);
        FKS(0, ldR[i], ldC[i] + 3) = split_tf32(kr[i].w);
        FVS(0, ldR[i], ldC[i] + 0) = split_tf32(vr[i].x);
        FVS(0, ldR[i], ldC[i] + 1) = split_tf32(vr[i].y);
        FVS(0, ldR[i], ldC[i] + 2) = split_tf32(vr[i].z);
        FVS(0, ldR[i], ldC[i] + 3) = split_tf32(vr[i].w);
    }
    __syncthreads();

    float co[4][4];
    #pragma unroll
    for (int nt = 0; nt < 4; nt++)
        #pragma unroll
        for (int i = 0; i < 4; i++) co[nt][i] = 0.f;
    float m_a = -INFINITY, m_b = -INFINITY, l_a = 0.f, l_b = 0.f;

    for (int j = 0; j < TPB; j++) {
        const int cur = j & 1;
        const int t0 = (tbase + j) * 64;

        if (j + 1 < TPB) {
            const int t1 = t0 + 64;
            #pragma unroll
            for (int i = 0; i < 4; i++) {
                size_t off = (size_t)(t1 + ldR[i]) * D + head * 32 + ldC[i];
                kr[i] = *(const float4*)&k[off];
                vr[i] = *(const float4*)&v[off];
            }
        }

        float cs[8][4];
        #pragma unroll
        for (int nt = 0; nt < 8; nt++)
            #pragma unroll
            for (int i = 0; i < 4; i++) cs[nt][i] = 0.f;

        #pragma unroll
        for (int k8 = 0; k8 < 4; k8++) {
            const int kk = k8 * 8;
            #pragma unroll
            for (int nt = 0; nt < 8; nt++) {
                int ci = nt * 8 + g;
                uint2 q0 = FKS(cur, ci, kk + tig);
                uint2 q1 = FKS(cur, ci, kk + tig + 4);
                uint32_t bH[2] = {q0.x, q1.x};
                uint32_t bL[2] = {q0.y, q1.y};
                mma3(cs[nt], aQH[k8], aQL[k8], bH, bL);
            }
        }

        float mx_a = m_a, mx_b = m_b;
        #pragma unroll
        for (int nt = 0; nt < 8; nt++) {
            int col0 = t0 + nt * 8 + 2 * tig;
            if (col0 >= S)     { cs[nt][0] = -INFINITY; cs[nt][2] = -INFINITY; }
            if (col0 + 1 >= S) { cs[nt][1] = -INFINITY; cs[nt][3] = -INFINITY; }
            mx_a = fmaxf(mx_a, fmaxf(cs[nt][0], cs[nt][1]));
            mx_b = fmaxf(mx_b, fmaxf(cs[nt][2], cs[nt][3]));
        }
        mx_a = fmaxf(mx_a, __shfl_xor_sync(0xffffffffu, mx_a, 1));
        mx_a = fmaxf(mx_a, __shfl_xor_sync(0xffffffffu, mx_a, 2));
        mx_b = fmaxf(mx_b, __shfl_xor_sync(0xffffffffu, mx_b, 1));
        mx_b = fmaxf(mx_b, __shfl_xor_sync(0xffffffffu, mx_b, 2));
        float corr_a = __expf(m_a - mx_a);
        float corr_b = __expf(m_b - mx_b);
        m_a = mx_a; m_b = mx_b;

        float la = 0.f, lb = 0.f;
        #pragma unroll
        for (int nt = 0; nt < 8; nt++) {
            cs[nt][0] = __expf(cs[nt][0] - m_a);
            cs[nt][1] = __expf(cs[nt][1] - m_a);
            cs[nt][2] = __expf(cs[nt][2] - m_b);
            cs[nt][3] = __expf(cs[nt][3] - m_b);
            la += cs[nt][0] + cs[nt][1];
            lb += cs[nt][2] + cs[nt][3];
        }
        la += __shfl_xor_sync(0xffffffffu, la, 1);
        la += __shfl_xor_sync(0xffffffffu, la, 2);
        lb += __shfl_xor_sync(0xffffffffu, lb, 1);
        lb += __shfl_xor_sync(0xffffffffu, lb, 2);
        l_a = l_a * corr_a + la;
        l_b = l_b * corr_b + lb;

        #pragma unroll
        for (int nt = 0; nt < 4; nt++) {
            co[nt][0] *= corr_a; co[nt][1] *= corr_a;
            co[nt][2] *= corr_b; co[nt][3] *= corr_b;
        }

        // PV: permute score C-frags -> A-frags via quad shuffles
        {
            const int s1 = (lane & ~3) | (tig >> 1);
            const int s2 = s1 + 2;
            const bool odd = (tig & 1) != 0;
            #pragma unroll
            for (int k8v = 0; k8v < 8; k8v++) {
                float q00 = __shfl_sync(0xffffffffu, cs[k8v][0], s1);
                float q01 = __shfl_sync(0xffffffffu, cs[k8v][1], s1);
                float q02 = __shfl_sync(0xffffffffu, cs[k8v][2], s1);
                float q03 = __shfl_sync(0xffffffffu, cs[k8v][3], s1);
                float r00 = __shfl_sync(0xffffffffu, cs[k8v][0], s2);
                float r01 = __shfl_sync(0xffffffffu, cs[k8v][1], s2);
                float r02 = __shfl_sync(0xffffffffu, cs[k8v][2], s2);
                float r03 = __shfl_sync(0xffffffffu, cs[k8v][3], s2);
                float a0 = odd ? q01 : q00;
                float a1 = odd ? q03 : q02;
                float a2 = odd ? r01 : r00;
                float a3 = odd ? r03 : r02;
                uint2 h0 = split_tf32(a0), h1 = split_tf32(a1);
                uint2 h2 = split_tf32(a2), h3 = split_tf32(a3);
                uint32_t aH[4] = {h0.x, h1.x, h2.x, h3.x};
                uint32_t aL[4] = {h0.y, h1.y, h2.y, h3.y};
                const int kkv = k8v * 8;
                #pragma unroll
                for (int nt = 0; nt < 4; nt++) {
                    uint2 q0 = FVS(cur, kkv + tig,     nt * 8 + g);
                    uint2 q1 = FVS(cur, kkv + tig + 4, nt * 8 + g);
                    uint32_t bH[2] = {q0.x, q1.x};
                    uint32_t bL[2] = {q0.y, q1.y};
                    mma3(co[nt], aH, aL, bH, bL);
                }
            }
        }

        if (j + 1 < TPB) {
            const int nb = (j + 1) & 1;
            #pragma unroll
            for (int i = 0; i < 4; i++) {
                FKS(nb, ldR[i], ldC[i] + 0) = split_tf32(kr[i].x);
                FKS(nb, ldR[i], ldC[i] + 1) = split_tf32(kr[i].y);
                FKS(nb, ldR[i], ldC[i] + 2) = split_tf32(kr[i].z);
                FKS(nb, ldR[i], ldC[i] + 3) = split_tf32(kr[i].w);
                FVS(nb, ldR[i], ldC[i] + 0) = split_tf32(vr[i].x);
                FVS(nb, ldR[i], ldC[i] + 1) = split_tf32(vr[i].y);
                FVS(nb, ldR[i], ldC[i] + 2) = split_tf32(vr[i].z);
                FVS(nb, ldR[i], ldC[i] + 3) = split_tf32(vr[i].w);
            }
            __syncthreads();
        }
    }

    float* po = g_po[z];
    int srow_a = s0 + wid * 16 + g;
    int srow_b = srow_a + 8;
    #pragma unroll
    for (int nt = 0; nt < 4; nt++) {
        int col = head * 32 + nt * 8 + 2 * tig;
        if (srow_a < S) {
            float2 w2 = make_float2(co[nt][0], co[nt][1]);
            *(float2*)&po[(size_t)srow_a * D + col] = w2;
        }
        if (srow_b < S) {
            float2 w2 = make_float2(co[nt][2], co[nt][3]);
            *(float2*)&po[(size_t)srow_b * D + col] = w2;
        }
    }
    if (tig == 0) {
        if (srow_a < S) g_pml[z][(size_t)srow_a * NHEAD + head] = make_float2(m_a, l_a);
        if (srow_b < S) g_pml[z][(size_t)srow_b * NHEAD + head] = make_float2(m_b, l_b);
    }
}

// combine kv-split partials -> o
__global__ void flash_combine_kernel(float* __restrict__ o) {
    int idx = blockIdx.x * 256 + threadIdx.x;
    if (idx >= SPAD * DIM) return;
    int row = idx >> 8;
    if (row >= S_ROWS) return;
    int head = (idx & 255) >> 5;
    float2 ml0 = g_pml[0][(size_t)row * NHEAD + head];
    float2 ml1 = g_pml[1][(size_t)row * NHEAD + head];
    float m = fmaxf(ml0.x, ml1.x);
    float e0 = __expf(ml0.x - m);
    float e1 = __expf(ml1.x - m);
    float l = ml0.y * e0 + ml1.y * e1;
    o[idx] = (g_po[0][idx] * e0 + g_po[1][idx] * e1) / l;
}

// ---------------- RQS spline ------------------------------------------------
__device__ __forceinline__ float softplusf(float x) {
    return (x > 20.f) ? x : log1pf(expf(x));
}

__global__ void spline_kernel(const float* __restrict__ pos,
                              const float* __restrict__ params,
                              float* __restrict__ out,
                              float* __restrict__ ld) {
    int s = blockIdx.x * blockDim.x + threadIdx.x;
    if (s >= S_ROWS) return;
    const float* p = params + s * AFF_OUT;
    const float MINB = 1e-4f;
    const float MINS = 1e-4f;

    float x = pos[(s + 1) * 3 + 2];
    bool inside = (x >= 0.f) && (x <= 1.f);
    float xc = fminf(fmaxf(x, 0.f), 1.f);

    float ew[NB], eh[NB];
    float mw = -INFINITY, mh = -INFINITY;
    #pragma unroll
    for (int i = 0; i < NB; i++) { mw = fmaxf(mw, p[i]); mh = fmaxf(mh, p[NB + i]); }
    float sw = 0.f, sh = 0.f;
    #pragma unroll
    for (int i = 0; i < NB; i++) {
        ew[i] = expf(p[i] - mw);        sw += ew[i];
        eh[i] = expf(p[NB + i] - mh);   sh += eh[i];
    }
    float fac = 1.f - NB * MINB;
    float isw = fac / sw, ish = fac / sh;

    float off = logf(expm1f(1.f - MINS));
    float d[NB + 1];
    #pragma unroll
    for (int i = 0; i < NB; i++) d[i] = softplusf(p[2 * NB + i] + off) + MINS;
    d[NB] = d[0];

    float xp[NB + 1], yp[NB + 1];
    xp[0] = 0.f; yp[0] = 0.f;
    #pragma unroll
    for (int i = 0; i < NB; i++) {
        xp[i + 1] = xp[i] + (ew[i] * isw + MINB);
        yp[i + 1] = yp[i] + (eh[i] * ish + MINB);
    }

    int cnt = 0;
    #pragma unroll
    for (int i = 0; i < NB + 1; i++) cnt += (xc >= xp[i]) ? 1 : 0;
    int kb = cnt - 1;
    if (kb < 0) kb = 0;
    if (kb > NB - 1) kb = NB - 1;

    float xk = xp[kb], xk1 = xp[kb + 1];
    float yk = yp[kb], yk1 = yp[kb + 1];
    float dk = d[kb],  dk1 = d[kb + 1];
    float w = xk1 - xk;
    float h = yk1 - yk;
    float sl = h / w;
    float z = (xc - xk) / w;
    float z1 = 1.f - z;
    float den = sl + (dk1 + dk - 2.f * sl) * z * z1;
    float y = yk + h * (sl * z * z + dk * z * z1) / den;
    float logdet = 2.f * logf(sl)
                 + logf(dk1 * z * z + 2.f * sl * z * z1 + dk * z1 * z1)
                 - 2.f * logf(den);

    out[(s + 1) * 3 + 2] = inside ? y : x;
    ld[s] = inside ? logdet : 0.f;
}

// ---------------- output copy + deterministic logdet reduction -------------
__global__ void copy_pos_kernel(const float* __restrict__ pos,
                                float* __restrict__ out, int n) {
    int i = blockIdx.x * blockDim.x + threadIdx.x;
    if (i < n) out[i] = pos[i];
}

__global__ void reduce_kernel(const float* __restrict__ ld,
                              float* __restrict__ out, int out_size) {
    __shared__ float sh[256];
    float s = 0.f;
    for (int i = threadIdx.x; i < S_ROWS; i += 256) s += ld[i];
    sh[threadIdx.x] = s;
    __syncthreads();
    for (int st = 128; st > 0; st >>= 1) {
        if (threadIdx.x < st) sh[threadIdx.x] += sh[threadIdx.x + st];
        __syncthreads();
    }
    if (threadIdx.x == 0 && out_size > POS_ELEMS) out[POS_ELEMS] = sh[0];
}

// ---------------- host orchestration ---------------------------------------
template <typename T>
static void* sym_addr_raw(T& sym) {
    void* p = nullptr;
    cudaGetSymbolAddress(&p, sym);
    return p;
}

static void gemm(const float* A, int lda, const uint2* B, const float* bias,
                 const float* res, float* C, int Nstore, int Npad, int Kp,
                 bool relu) {
    dim3 grid(Npad / 64, SPAD / 32);
    if (relu)
        gemm_v6_kernel<true ><<<grid, 256, GEMM_SMEM>>>(A, lda, B, bias, res,
                                                        C, Nstore, Kp);
    else
        gemm_v6_kernel<false><<<grid, 256, GEMM_SMEM>>>(A, lda, B, bias, res,
                                                        C, Nstore, Kp);
}

extern "C" void kernel_launch(void* const* d_in, const int* in_sizes, int n_in,
                              void* d_out, int out_size) {
    const float* pos   = (const float*)d_in[0];
    const float* scale = (const float*)d_in[1];
    const float* press = (const float*)d_in[2];
    const float* temp  = (const float*)d_in[3];
    const float* e_w0 = (const float*)d_in[4];
    const float* e_b0 = (const float*)d_in[5];
    const float* e_w1 = (const float*)d_in[6];
    const float* e_b1 = (const float*)d_in[7];
    const float* e_w2 = (const float*)d_in[8];
    const float* e_b2 = (const float*)d_in[9];
    const float* Wq   = (const float*)d_in[10];
    const float* Wk   = (const float*)d_in[11];
    const float* bk   = (const float*)d_in[12];
    const float* Wv   = (const float*)d_in[13];
    const float* Wo   = (const float*)d_in[14];
    const float* bo   = (const float*)d_in[15];
    const float* mw0  = (const float*)d_in[16];
    const float* mb0  = (const float*)d_in[17];
    const float* mw1  = (const float*)d_in[18];
    const float* mb1  = (const float*)d_in[19];
    const float* mw2  = (const float*)d_in[20];
    const float* mb2  = (const float*)d_in[21];
    const float* a_w0 = (const float*)d_in[22];
    const float* a_b0 = (const float*)d_in[23];
    const float* a_w1 = (const float*)d_in[24];
    const float* a_b1 = (const float*)d_in[25];
    const float* a_w2 = (const float*)d_in[26];
    const float* a_b2 = (const float*)d_in[27];

    const uint2* ws = (const uint2*)sym_addr_raw(g_wsplit);
    float* cond   = (float*)sym_addr_raw(g_cond);
    float* bufA   = (float*)sym_addr_raw(g_a);
    float* bufB   = (float*)sym_addr_raw(g_b);
    float* h      = (float*)sym_addr_raw(g_h);
    float* t      = (float*)sym_addr_raw(g_t);
    float* q      = (float*)sym_addr_raw(g_q);
    float* k      = (float*)sym_addr_raw(g_k);
    float* v      = (float*)sym_addr_raw(g_v);
    float* params = (float*)sym_addr_raw(g_params);
    float* ld     = (float*)sym_addr_raw(g_ld);
    float* out    = (float*)d_out;

    cudaFuncSetAttribute(gemm_v6_kernel<true>,
                         cudaFuncAttributeMaxDynamicSharedMemorySize, GEMM_SMEM);
    cudaFuncSetAttribute(gemm_v6_kernel<false>,
                         cudaFuncAttributeMaxDynamicSharedMemorySize, GEMM_SMEM);
    cudaFuncSetAttribute(gemm_qkv_kernel,
                         cudaFuncAttributeMaxDynamicSharedMemorySize, GEMM_SMEM);
    cudaFuncSetAttribute(flash_mma_kernel,
                         cudaFuncAttributeMaxDynamicSharedMemorySize, FLASH_SMEM);

    // presplit all weights (one flat launch)
    wsplit_kernel<<<(WSPLIT_TOTAL + 255) / 256, 256>>>(
        e_w0, e_w1, e_w2, Wq, Wk, Wv, Wo, mw0, mw1, mw2, a_w0, a_w1, a_w2);

    embed_kernel<<<SPAD / 256, 256>>>(pos, scale, press, temp, cond);

    // embedding MLP: 35 -> 512 -> 512 -> 256
    gemm(cond, CONDP, ws + OFF_EW0, e_b0, nullptr, bufA, HID, HID, CONDP, true);
    gemm(bufA, HID,   ws + OFF_EW1, e_b1, nullptr, bufB, HID, HID, HID, true);
    gemm(bufB, HID,   ws + OFF_EW2, e_b2, nullptr, h,    DIM, DIM, HID, false);

    for (int i = 0; i < NBLK; i++) {
        const float* bki = bk + (size_t)i * DIM;
        const float* boi = bo + (size_t)i * DIM;
        const float* mb0i = mb0 + (size_t)i * HID;
        const float* mb1i = mb1 + (size_t)i * HID;
        const float* mb2i = mb2 + (size_t)i * DIM;

        dim3 qkvgrid(DIM / 64, SPAD / 32, 3);
        gemm_qkv_kernel<<<qkvgrid, 256, GEMM_SMEM>>>(h, i * DIM * DIM, bki,
                                                     q, k, v);

        dim3 fgrid((S_ROWS + 63) / 64, NHEAD, KVSPLIT);
        flash_mma_kernel<<<fgrid, 128, FLASH_SMEM>>>(q, k, v);
        flash_combine_kernel<<<SPAD * DIM / 256, 256>>>(t);

        gemm(t, DIM, ws + OFF_WO + i * DIM * DIM, boi, h, h, DIM, DIM, DIM, false);

        gemm(h,    DIM, ws + OFF_MW0 + i * HID * DIM, mb0i, nullptr, bufA, HID, HID, DIM, true);
        gemm(bufA, HID, ws + OFF_MW1 + i * HID * HID, mb1i, nullptr, bufB, HID, HID, HID, true);
        gemm(bufB, HID, ws + OFF_MW2 + i * DIM * HID, mb2i, h,       h,    DIM, DIM, HID, false);
    }

    // affine head: 256 -> 512 -> 512 -> 49
    gemm(h,    DIM, ws + OFF_AW0, a_b0, nullptr, bufA,   HID,     HID, DIM, true);
    gemm(bufA, HID, ws + OFF_AW1, a_b1, nullptr, bufB,   HID,     HID, HID, true);
    gemm(bufB, HID, ws + OFF_AW2, a_b2, nullptr, params, AFF_OUT, 64,  HID, false);

    int ncopy = out_size < POS_ELEMS ? out_size : POS_ELEMS;
    copy_pos_kernel<<<(ncopy + 255) / 256, 256>>>(pos, out, ncopy);
    spline_kernel<<<(S_ROWS + 255) / 256, 256>>>(pos, params, out, ld);
    reduce_kernel<<<1, 256>>>(ld, out, out_size);
}

// round 9
// speedup vs baseline: 1.1926x; 1.1926x over previous
#include <cuda_runtime.h>
#include <cstdint>
#include <math.h>

// ---------------- problem constants ----------------
#define S_ROWS 2047          // N_PART - 1
#define SPAD   2048
#define DIM    256
#define HID    512
#define NB     16
#define NFREQ  8
#define NBLK   4
#define NHEAD  8
#define EMB_IN 35
#define CONDP  64            // padded cond width
#define AFF_OUT 49
#define POS_ELEMS (2048*3)
#define KVSPLIT 2

// gemm smem: As[2][64][36] + Bs[2][64][36] uint2
#define GEMM_SMEM ((2*64*36 + 2*64*36) * 8)
// flash smem: Ks[2][64][36] + Vs[2][64][36] uint2
#define FLASH_SMEM ((2*64*36 + 2*64*36) * 8)

// ---------------- scratch (static device memory; zero-initialized) --------
__device__ float g_cond[SPAD * CONDP];
__device__ float g_a[SPAD * HID];
__device__ float g_b[SPAD * HID];
__device__ float g_h[SPAD * DIM];
__device__ float g_t[SPAD * DIM];
__device__ float g_q[SPAD * DIM];
__device__ float g_k[SPAD * DIM];
__device__ float g_v[SPAD * DIM];
__device__ float g_po[KVSPLIT][SPAD * DIM];
__device__ float2 g_pml[KVSPLIT][SPAD * NHEAD];
__device__ float g_params[SPAD * AFF_OUT];
__device__ float g_ld[S_ROWS];

// ---------------- helpers ---------------------------------------------------
__device__ __forceinline__ uint32_t f2tf32(float f) {
    uint32_t u;
    asm("cvt.rna.tf32.f32 %0, %1;" : "=r"(u) : "f"(f));
    return u;
}

__device__ __forceinline__ uint2 split_tf32(float f) {
    uint32_t hi = f2tf32(f);
    uint32_t lo = f2tf32(f - __uint_as_float(hi));
    return make_uint2(hi, lo);
}

__device__ __forceinline__ void mma_tf32(float c[4], const uint32_t a[4],
                                         const uint32_t b[2]) {
    asm volatile(
        "mma.sync.aligned.m16n8k8.row.col.f32.tf32.tf32.f32 "
        "{%0,%1,%2,%3}, {%4,%5,%6,%7}, {%8,%9}, {%0,%1,%2,%3};"
        : "+f"(c[0]), "+f"(c[1]), "+f"(c[2]), "+f"(c[3])
        : "r"(a[0]), "r"(a[1]), "r"(a[2]), "r"(a[3]), "r"(b[0]), "r"(b[1]));
}

__device__ __forceinline__ void mma3(float c[4], const uint32_t aH[4],
                                     const uint32_t aL[4], const uint32_t bH[2],
                                     const uint32_t bL[2]) {
    mma_tf32(c, aL, bH);
    mma_tf32(c, aH, bL);
    mma_tf32(c, aH, bH);
}

// ---------------- circular features (padded cond) ----------------------------
__global__ void embed_kernel(const float* __restrict__ pos,
                             const float* __restrict__ scale,
                             const float* __restrict__ press,
                             const float* __restrict__ temp,
                             float* __restrict__ cond) {
    int s = blockIdx.x * blockDim.x + threadIdx.x;
    if (s >= SPAD) return;
    float* c = cond + s * CONDP;
    if (s >= S_ROWS) {
        #pragma unroll
        for (int i = 0; i < CONDP; i++) c[i] = 0.f;
        return;
    }
    const float TWO_PI = 6.28318530717958647692f;
    float xs[2];
    xs[0] = pos[(s + 1) * 3 + 0];
    xs[1] = pos[(s + 1) * 3 + 1];
    #pragma unroll
    for (int cc = 0; cc < 2; cc++) {
        float x = xs[cc];
        #pragma unroll
        for (int f = 1; f <= NFREQ; f++) {
            float sn, cs;
            sincosf(TWO_PI * (float)f * x, &sn, &cs);
            c[cc * 16 + (f - 1)]     = cs;
            c[cc * 16 + 8 + (f - 1)] = sn;
        }
    }
    c[32] = *scale;
    c[33] = *temp;
    c[34] = *press;
    #pragma unroll
    for (int i = EMB_IN; i < CONDP; i++) c[i] = 0.f;
}

// ---------------- GEMM v7: 64x64 tile, double-buffered, prefetch -------------
// C[2047 x Nstore] = A[2048 x lda] @ W[Nstore x Kreal]^T (+bias)(+res)(relu)
// 256 thr (8 warps, 2m x 4n), warp tile 32x16.
#define GAS(b,r,c) sm[((b)*64 + (r))*36 + (c)]
#define GBS(b,r,c) sm[4608 + ((b)*64 + (r))*36 + (c)]

template <bool RELU, bool FULL>
__device__ __forceinline__
void gemm_core(const float* __restrict__ A, int lda,
               const float* __restrict__ W,
               const float* __restrict__ bias, const float* __restrict__ res,
               float* __restrict__ C, int Nstore, int Kreal, int Kp) {
    extern __shared__ uint2 sm[];

    const int tid  = threadIdx.x;
    const int lane = tid & 31;
    const int wid  = tid >> 5;
    const int warp_m = wid >> 2;        // 0..1 (32 rows)
    const int warp_n = wid & 3;         // 0..3 (16 cols)
    const int g   = lane >> 2;
    const int tig = lane & 3;

    const int m0 = blockIdx.y * 64;
    const int n0 = blockIdx.x * 64;

    // load mapping: 64x32 floats/stage per operand, 2 float4 per thread
    int ldRow[2], ldCol[2];
    #pragma unroll
    for (int i = 0; i < 2; i++) {
        int f4 = i * 256 + tid;
        ldRow[i] = f4 >> 3;             // 0..63
        ldCol[i] = (f4 & 7) * 4;
    }
    const int stages = Kp >> 5;

    float av[2][4], bv[2][4];

    // ---- prologue: load stage 0, commit to buf 0 ----
    {
        #pragma unroll
        for (int i = 0; i < 2; i++) {
            float4 a4 = *(const float4*)(A + (size_t)(m0 + ldRow[i]) * lda + ldCol[i]);
            av[i][0] = a4.x; av[i][1] = a4.y; av[i][2] = a4.z; av[i][3] = a4.w;
            if (FULL) {
                float4 w4 = *(const float4*)(W + (size_t)(n0 + ldRow[i]) * Kreal + ldCol[i]);
                bv[i][0] = w4.x; bv[i][1] = w4.y; bv[i][2] = w4.z; bv[i][3] = w4.w;
            } else {
                int n = n0 + ldRow[i];
                #pragma unroll
                for (int j = 0; j < 4; j++) {
                    int kk = ldCol[i] + j;
                    bv[i][j] = (n < Nstore && kk < Kreal)
                             ? W[(size_t)n * Kreal + kk] : 0.f;
                }
            }
        }
        #pragma unroll
        for (int i = 0; i < 2; i++)
            #pragma unroll
            for (int j = 0; j < 4; j++) {
                GAS(0, ldRow[i], ldCol[i] + j) = split_tf32(av[i][j]);
                GBS(0, ldRow[i], ldCol[i] + j) = split_tf32(bv[i][j]);
            }
    }
    __syncthreads();

    float acc[2][2][4];
    #pragma unroll
    for (int mt = 0; mt < 2; mt++)
        #pragma unroll
        for (int nt = 0; nt < 2; nt++)
            #pragma unroll
            for (int i = 0; i < 4; i++) acc[mt][nt][i] = 0.f;

    for (int s = 0; s < stages; s++) {
        const int cur = s & 1;

        // prefetch next stage into registers (overlaps with mma)
        if (s + 1 < stages) {
            const int k0 = (s + 1) * 32;
            #pragma unroll
            for (int i = 0; i < 2; i++) {
                float4 a4 = *(const float4*)(A + (size_t)(m0 + ldRow[i]) * lda + k0 + ldCol[i]);
                av[i][0] = a4.x; av[i][1] = a4.y; av[i][2] = a4.z; av[i][3] = a4.w;
                if (FULL) {
                    float4 w4 = *(const float4*)(W + (size_t)(n0 + ldRow[i]) * Kreal + k0 + ldCol[i]);
                    bv[i][0] = w4.x; bv[i][1] = w4.y; bv[i][2] = w4.z; bv[i][3] = w4.w;
                } else {
                    int n = n0 + ldRow[i];
                    #pragma unroll
                    for (int j = 0; j < 4; j++) {
                        int kk = k0 + ldCol[i] + j;
                        bv[i][j] = (n < Nstore && kk < Kreal)
                                 ? W[(size_t)n * Kreal + kk] : 0.f;
                    }
                }
            }
        }

        // mma over current buffer
        #pragma unroll
        for (int k8 = 0; k8 < 4; k8++) {
            const int kk = k8 * 8;
            uint32_t aH[2][4], aL[2][4];
            #pragma unroll
            for (int mt = 0; mt < 2; mt++) {
                const int r = warp_m * 32 + mt * 16 + g;
                uint2 p0 = GAS(cur, r,     kk + tig);
                uint2 p1 = GAS(cur, r + 8, kk + tig);
                uint2 p2 = GAS(cur, r,     kk + tig + 4);
                uint2 p3 = GAS(cur, r + 8, kk + tig + 4);
                aH[mt][0] = p0.x; aH[mt][1] = p1.x; aH[mt][2] = p2.x; aH[mt][3] = p3.x;
                aL[mt][0] = p0.y; aL[mt][1] = p1.y; aL[mt][2] = p2.y; aL[mt][3] = p3.y;
            }
            uint32_t bH[2][2], bL[2][2];
            #pragma unroll
            for (int nt = 0; nt < 2; nt++) {
                int ci = warp_n * 16 + nt * 8 + g;
                uint2 q0 = GBS(cur, ci, kk + tig);
                uint2 q1 = GBS(cur, ci, kk + tig + 4);
                bH[nt][0] = q0.x; bH[nt][1] = q1.x;
                bL[nt][0] = q0.y; bL[nt][1] = q1.y;
            }
            #pragma unroll
            for (int mt = 0; mt < 2; mt++)
                #pragma unroll
                for (int nt = 0; nt < 2; nt++)
                    mma3(acc[mt][nt], aH[mt], aL[mt], bH[nt], bL[nt]);
        }

        // commit next stage into the other buffer
        if (s + 1 < stages) {
            const int nb = (s + 1) & 1;
            #pragma unroll
            for (int i = 0; i < 2; i++)
                #pragma unroll
                for (int j = 0; j < 4; j++) {
                    GAS(nb, ldRow[i], ldCol[i] + j) = split_tf32(av[i][j]);
                    GBS(nb, ldRow[i], ldCol[i] + j) = split_tf32(bv[i][j]);
                }
        }
        __syncthreads();
    }

    // epilogue
    #pragma unroll
    for (int mt = 0; mt < 2; mt++) {
        #pragma unroll
        for (int nt = 0; nt < 2; nt++) {
            int r0 = m0 + warp_m * 32 + mt * 16 + g;
            int cb = n0 + warp_n * 16 + nt * 8 + tig * 2;
            #pragma unroll
            for (int half = 0; half < 2; half++) {
                int r = r0 + half * 8;
                if (r >= S_ROWS) continue;
                #pragma unroll
                for (int j = 0; j < 2; j++) {
                    int n = cb + j;
                    if (n >= Nstore) continue;
                    float v = acc[mt][nt][half * 2 + j];
                    if (bias) v += bias[n];
                    if (res)  v += res[(size_t)r * Nstore + n];
                    if (RELU) v = fmaxf(v, 0.f);
                    C[(size_t)r * Nstore + n] = v;
                }
            }
        }
    }
}

template <bool RELU, bool FULL>
__global__ __launch_bounds__(256)
void gemm_v7_kernel(const float* __restrict__ A, int lda,
                    const float* __restrict__ W,
                    const float* __restrict__ bias, const float* __restrict__ res,
                    float* __restrict__ C, int Nstore, int Kreal, int Kp) {
    gemm_core<RELU, FULL>(A, lda, W, bias, res, C, Nstore, Kreal, Kp);
}

// fused q/k/v projection via blockIdx.z
__global__ __launch_bounds__(256)
void gemm_qkv_kernel(const float* __restrict__ h,
                     const float* __restrict__ Wq, const float* __restrict__ Wk,
                     const float* __restrict__ Wv, const float* __restrict__ bk,
                     float* __restrict__ q, float* __restrict__ k,
                     float* __restrict__ v) {
    int z = blockIdx.z;
    const float* W = (z == 0) ? Wq : (z == 1) ? Wk : Wv;
    const float* bias = (z == 1) ? bk : nullptr;
    float* C = (z == 0) ? q : (z == 1) ? k : v;
    gemm_core<false, true>(h, DIM, W, bias, nullptr, C, DIM, DIM, DIM);
}

// ---------------- flash attention (r7: register-P + kv-split) ---------------
#define FKS(b,r,c) sm[((b)*64 + (r))*36 + (c)]
#define FVS(b,r,c) sm[4608 + ((b)*64 + (r))*36 + (c)]

__global__ __launch_bounds__(128)
void flash_mma_kernel(const float* __restrict__ q,
                      const float* __restrict__ k,
                      const float* __restrict__ v) {
    extern __shared__ uint2 sm[];

    const int S = S_ROWS, D = DIM;
    const int head = blockIdx.y;
    const int z = blockIdx.z;
    const int s0 = blockIdx.x * 64;
    const int tid = threadIdx.x;
    const int lane = tid & 31;
    const int wid = tid >> 5;
    const int g = lane >> 2;
    const int tig = lane & 3;
    const float scl = 0.17677669529663688f;
    const int TPB = 32 / KVSPLIT;
    const int tbase = z * TPB;

    uint32_t aQH[4][4], aQL[4][4];
    {
        const int ra = s0 + wid * 16 + g;
        const int rb = ra + 8;
        #pragma unroll
        for (int k8 = 0; k8 < 4; k8++) {
            const int c0 = head * 32 + k8 * 8 + tig;
            uint2 p0 = split_tf32(q[(size_t)ra * D + c0] * scl);
            uint2 p1 = split_tf32(q[(size_t)rb * D + c0] * scl);
            uint2 p2 = split_tf32(q[(size_t)ra * D + c0 + 4] * scl);
            uint2 p3 = split_tf32(q[(size_t)rb * D + c0 + 4] * scl);
            aQH[k8][0] = p0.x; aQH[k8][1] = p1.x; aQH[k8][2] = p2.x; aQH[k8][3] = p3.x;
            aQL[k8][0] = p0.y; aQL[k8][1] = p1.y; aQL[k8][2] = p2.y; aQL[k8][3] = p3.y;
        }
    }

    float4 kr[4], vr[4];
    int ldR[4], ldC[4];
    #pragma unroll
    for (int i = 0; i < 4; i++) {
        int cc = i * 128 + tid;
        ldR[i] = cc >> 3;
        ldC[i] = (cc & 7) * 4;
    }

    #pragma unroll
    for (int i = 0; i < 4; i++) {
        size_t off = (size_t)(tbase * 64 + ldR[i]) * D + head * 32 + ldC[i];
        kr[i] = *(const float4*)&k[off];
        vr[i] = *(const float4*)&v[off];
    }
    #pragma unroll
    for (int i = 0; i < 4; i++) {
        FKS(0, ldR[i], ldC[i] + 0) = split_tf32(kr[i].x);
        FKS(0, ldR[i], ldC[i] + 1) = split_tf32(kr[i].y);
        FKS(0, ldR[i], ldC[i] + 2) = split_tf32(kr[i].z);
        FKS(0, ldR[i], ldC[i] + 3) = split_tf32(kr[i].w);
        FVS(0, ldR[i], ldC[i] + 0) = split_tf32(vr[i].x);
        FVS(0, ldR[i], ldC[i] + 1) = split_tf32(vr[i].y);
        FVS(0, ldR[i], ldC[i] + 2) = split_tf32(vr[i].z);
        FVS(0, ldR[i], ldC[i] + 3) = split_tf32(vr[i].w);
    }
    __syncthreads();

    float co[4][4];
    #pragma unroll
    for (int nt = 0; nt < 4; nt++)
        #pragma unroll
        for (int i = 0; i < 4; i++) co[nt][i] = 0.f;
    float m_a = -INFINITY, m_b = -INFINITY, l_a = 0.f, l_b = 0.f;

    for (int j = 0; j < TPB; j++) {
        const int cur = j & 1;
        const int t0 = (tbase + j) * 64;

        if (j + 1 < TPB) {
            const int t1 = t0 + 64;
            #pragma unroll
            for (int i = 0; i < 4; i++) {
                size_t off = (size_t)(t1 + ldR[i]) * D + head * 32 + ldC[i];
                kr[i] = *(const float4*)&k[off];
                vr[i] = *(const float4*)&v[off];
            }
        }

        float cs[8][4];
        #pragma unroll
        for (int nt = 0; nt < 8; nt++)
            #pragma unroll
            for (int i = 0; i < 4; i++) cs[nt][i] = 0.f;

        #pragma unroll
        for (int k8 = 0; k8 < 4; k8++) {
            const int kk = k8 * 8;
            #pragma unroll
            for (int nt = 0; nt < 8; nt++) {
                int ci = nt * 8 + g;
                uint2 q0 = FKS(cur, ci, kk + tig);
                uint2 q1 = FKS(cur, ci, kk + tig + 4);
                uint32_t bH[2] = {q0.x, q1.x};
                uint32_t bL[2] = {q0.y, q1.y};
                mma3(cs[nt], aQH[k8], aQL[k8], bH, bL);
            }
        }

        float mx_a = m_a, mx_b = m_b;
        #pragma unroll
        for (int nt = 0; nt < 8; nt++) {
            int col0 = t0 + nt * 8 + 2 * tig;
            if (col0 >= S)     { cs[nt][0] = -INFINITY; cs[nt][2] = -INFINITY; }
            if (col0 + 1 >= S) { cs[nt][1] = -INFINITY; cs[nt][3] = -INFINITY; }
            mx_a = fmaxf(mx_a, fmaxf(cs[nt][0], cs[nt][1]));
            mx_b = fmaxf(mx_b, fmaxf(cs[nt][2], cs[nt][3]));
        }
        mx_a = fmaxf(mx_a, __shfl_xor_sync(0xffffffffu, mx_a, 1));
        mx_a = fmaxf(mx_a, __shfl_xor_sync(0xffffffffu, mx_a, 2));
        mx_b = fmaxf(mx_b, __shfl_xor_sync(0xffffffffu, mx_b, 1));
        mx_b = fmaxf(mx_b, __shfl_xor_sync(0xffffffffu, mx_b, 2));
        float corr_a = __expf(m_a - mx_a);
        float corr_b = __expf(m_b - mx_b);
        m_a = mx_a; m_b = mx_b;

        float la = 0.f, lb = 0.f;
        #pragma unroll
        for (int nt = 0; nt < 8; nt++) {
            cs[nt][0] = __expf(cs[nt][0] - m_a);
            cs[nt][1] = __expf(cs[nt][1] - m_a);
            cs[nt][2] = __expf(cs[nt][2] - m_b);
            cs[nt][3] = __expf(cs[nt][3] - m_b);
            la += cs[nt][0] + cs[nt][1];
            lb += cs[nt][2] + cs[nt][3];
        }
        la += __shfl_xor_sync(0xffffffffu, la, 1);
        la += __shfl_xor_sync(0xffffffffu, la, 2);
        lb += __shfl_xor_sync(0xffffffffu, lb, 1);
        lb += __shfl_xor_sync(0xffffffffu, lb, 2);
        l_a = l_a * corr_a + la;
        l_b = l_b * corr_b + lb;

        #pragma unroll
        for (int nt = 0; nt < 4; nt++) {
            co[nt][0] *= corr_a; co[nt][1] *= corr_a;
            co[nt][2] *= corr_b; co[nt][3] *= corr_b;
        }

        {
            const int s1 = (lane & ~3) | (tig >> 1);
            const int s2 = s1 + 2;
            const bool odd = (tig & 1) != 0;
            #pragma unroll
            for (int k8v = 0; k8v < 8; k8v++) {
                float q00 = __shfl_sync(0xffffffffu, cs[k8v][0], s1);
                float q01 = __shfl_sync(0xffffffffu, cs[k8v][1], s1);
                float q02 = __shfl_sync(0xffffffffu, cs[k8v][2], s1);
                float q03 = __shfl_sync(0xffffffffu, cs[k8v][3], s1);
                float r00 = __shfl_sync(0xffffffffu, cs[k8v][0], s2);
                float r01 = __shfl_sync(0xffffffffu, cs[k8v][1], s2);
                float r02 = __shfl_sync(0xffffffffu, cs[k8v][2], s2);
                float r03 = __shfl_sync(0xffffffffu, cs[k8v][3], s2);
                float a0 = odd ? q01 : q00;
                float a1 = odd ? q03 : q02;
                float a2 = odd ? r01 : r00;
                float a3 = odd ? r03 : r02;
                uint2 h0 = split_tf32(a0), h1 = split_tf32(a1);
                uint2 h2 = split_tf32(a2), h3 = split_tf32(a3);
                uint32_t aH[4] = {h0.x, h1.x, h2.x, h3.x};
                uint32_t aL[4] = {h0.y, h1.y, h2.y, h3.y};
                const int kkv = k8v * 8;
                #pragma unroll
                for (int nt = 0; nt < 4; nt++) {
                    uint2 q0 = FVS(cur, kkv + tig,     nt * 8 + g);
                    uint2 q1 = FVS(cur, kkv + tig + 4, nt * 8 + g);
                    uint32_t bH[2] = {q0.x, q1.x};
                    uint32_t bL[2] = {q0.y, q1.y};
                    mma3(co[nt], aH, aL, bH, bL);
                }
            }
        }

        if (j + 1 < TPB) {
            const int nb = (j + 1) & 1;
            #pragma unroll
            for (int i = 0; i < 4; i++) {
                FKS(nb, ldR[i], ldC[i] + 0) = split_tf32(kr[i].x);
                FKS(nb, ldR[i], ldC[i] + 1) = split_tf32(kr[i].y);
                FKS(nb, ldR[i], ldC[i] + 2) = split_tf32(kr[i].z);
                FKS(nb, ldR[i], ldC[i] + 3) = split_tf32(kr[i].w);
                FVS(nb, ldR[i], ldC[i] + 0) = split_tf32(vr[i].x);
                FVS(nb, ldR[i], ldC[i] + 1) = split_tf32(vr[i].y);
                FVS(nb, ldR[i], ldC[i] + 2) = split_tf32(vr[i].z);
                FVS(nb, ldR[i], ldC[i] + 3) = split_tf32(vr[i].w);
            }
            __syncthreads();
        }
    }

    float* po = g_po[z];
    int srow_a = s0 + wid * 16 + g;
    int srow_b = srow_a + 8;
    #pragma unroll
    for (int nt = 0; nt < 4; nt++) {
        int col = head * 32 + nt * 8 + 2 * tig;
        if (srow_a < S) {
            float2 w2 = make_float2(co[nt][0], co[nt][1]);
            *(float2*)&po[(size_t)srow_a * D + col] = w2;
        }
        if (srow_b < S) {
            float2 w2 = make_float2(co[nt][2], co[nt][3]);
            *(float2*)&po[(size_t)srow_b * D + col] = w2;
        }
    }
    if (tig == 0) {
        if (srow_a < S) g_pml[z][(size_t)srow_a * NHEAD + head] = make_float2(m_a, l_a);
        if (srow_b < S) g_pml[z][(size_t)srow_b * NHEAD + head] = make_float2(m_b, l_b);
    }
}

// combine kv-split partials -> o
__global__ void flash_combine_kernel(float* __restrict__ o) {
    int idx = blockIdx.x * 256 + threadIdx.x;
    if (idx >= SPAD * DIM) return;
    int row = idx >> 8;
    if (row >= S_ROWS) return;
    int head = (idx & 255) >> 5;
    float2 ml0 = g_pml[0][(size_t)row * NHEAD + head];
    float2 ml1 = g_pml[1][(size_t)row * NHEAD + head];
    float m = fmaxf(ml0.x, ml1.x);
    float e0 = __expf(ml0.x - m);
    float e1 = __expf(ml1.x - m);
    float l = ml0.y * e0 + ml1.y * e1;
    o[idx] = (g_po[0][idx] * e0 + g_po[1][idx] * e1) / l;
}

// ---------------- RQS spline ------------------------------------------------
__device__ __forceinline__ float softplusf(float x) {
    return (x > 20.f) ? x : log1pf(expf(x));
}

__global__ void spline_kernel(const float* __restrict__ pos,
                              const float* __restrict__ params,
                              float* __restrict__ out,
                              float* __restrict__ ld) {
    int s = blockIdx.x * blockDim.x + threadIdx.x;
    if (s >= S_ROWS) return;
    const float* p = params + s * AFF_OUT;
    const float MINB = 1e-4f;
    const float MINS = 1e-4f;

    float x = pos[(s + 1) * 3 + 2];
    bool inside = (x >= 0.f) && (x <= 1.f);
    float xc = fminf(fmaxf(x, 0.f), 1.f);

    float ew[NB], eh[NB];
    float mw = -INFINITY, mh = -INFINITY;
    #pragma unroll
    for (int i = 0; i < NB; i++) { mw = fmaxf(mw, p[i]); mh = fmaxf(mh, p[NB + i]); }
    float sw = 0.f, sh = 0.f;
    #pragma unroll
    for (int i = 0; i < NB; i++) {
        ew[i] = expf(p[i] - mw);        sw += ew[i];
        eh[i] = expf(p[NB + i] - mh);   sh += eh[i];
    }
    float fac = 1.f - NB * MINB;
    float isw = fac / sw, ish = fac / sh;

    float off = logf(expm1f(1.f - MINS));
    float d[NB + 1];
    #pragma unroll
    for (int i = 0; i < NB; i++) d[i] = softplusf(p[2 * NB + i] + off) + MINS;
    d[NB] = d[0];

    float xp[NB + 1], yp[NB + 1];
    xp[0] = 0.f; yp[0] = 0.f;
    #pragma unroll
    for (int i = 0; i < NB; i++) {
        xp[i + 1] = xp[i] + (ew[i] * isw + MINB);
        yp[i + 1] = yp[i] + (eh[i] * ish + MINB);
    }

    int cnt = 0;
    #pragma unroll
    for (int i = 0; i < NB + 1; i++) cnt += (xc >= xp[i]) ? 1 : 0;
    int kb = cnt - 1;
    if (kb < 0) kb = 0;
    if (kb > NB - 1) kb = NB - 1;

    float xk = xp[kb], xk1 = xp[kb + 1];
    float yk = yp[kb], yk1 = yp[kb + 1];
    float dk = d[kb],  dk1 = d[kb + 1];
    float w = xk1 - xk;
    float h = yk1 - yk;
    float sl = h / w;
    float z = (xc - xk) / w;
    float z1 = 1.f - z;
    float den = sl + (dk1 + dk - 2.f * sl) * z * z1;
    float y = yk + h * (sl * z * z + dk * z * z1) / den;
    float logdet = 2.f * logf(sl)
                 + logf(dk1 * z * z + 2.f * sl * z * z1 + dk * z1 * z1)
                 - 2.f * logf(den);

    out[(s + 1) * 3 + 2] = inside ? y : x;
    ld[s] = inside ? logdet : 0.f;
}

// ---------------- output copy + deterministic logdet reduction -------------
__global__ void copy_pos_kernel(const float* __restrict__ pos,
                                float* __restrict__ out, int n) {
    int i = blockIdx.x * blockDim.x + threadIdx.x;
    if (i < n) out[i] = pos[i];
}

__global__ void reduce_kernel(const float* __restrict__ ld,
                              float* __restrict__ out, int out_size) {
    __shared__ float sh[256];
    float s = 0.f;
    for (int i = threadIdx.x; i < S_ROWS; i += 256) s += ld[i];
    sh[threadIdx.x] = s;
    __syncthreads();
    for (int st = 128; st > 0; st >>= 1) {
        if (threadIdx.x < st) sh[threadIdx.x] += sh[threadIdx.x + st];
        __syncthreads();
    }
    if (threadIdx.x == 0 && out_size > POS_ELEMS) out[POS_ELEMS] = sh[0];
}

// ---------------- host orchestration ---------------------------------------
template <typename T>
static void* sym_addr_raw(T& sym) {
    void* p = nullptr;
    cudaGetSymbolAddress(&p, sym);
    return p;
}

static void gemm(const float* A, int lda, const float* W, const float* bias,
                 const float* res, float* C, int Nstore, int Npad,
                 int Kreal, int Kp, bool relu) {
    dim3 grid(Npad / 64, SPAD / 64);
    bool full = (Nstore % 64 == 0) && (Kreal == Kp);
    if (full) {
        if (relu)
            gemm_v7_kernel<true , true ><<<grid, 256, GEMM_SMEM>>>(A, lda, W, bias, res, C, Nstore, Kreal, Kp);
        else
            gemm_v7_kernel<false, true ><<<grid, 256, GEMM_SMEM>>>(A, lda, W, bias, res, C, Nstore, Kreal, Kp);
    } else {
        if (relu)
            gemm_v7_kernel<true , false><<<grid, 256, GEMM_SMEM>>>(A, lda, W, bias, res, C, Nstore, Kreal, Kp);
        else
            gemm_v7_kernel<false, false><<<grid, 256, GEMM_SMEM>>>(A, lda, W, bias, res, C, Nstore, Kreal, Kp);
    }
}

extern "C" void kernel_launch(void* const* d_in, const int* in_sizes, int n_in,
                              void* d_out, int out_size) {
    const float* pos   = (const float*)d_in[0];
    const float* scale = (const float*)d_in[1];
    const float* press = (const float*)d_in[2];
    const float* temp  = (const float*)d_in[3];
    const float* e_w0 = (const float*)d_in[4];
    const float* e_b0 = (const float*)d_in[5];
    const float* e_w1 = (const float*)d_in[6];
    const float* e_b1 = (const float*)d_in[7];
    const float* e_w2 = (const float*)d_in[8];
    const float* e_b2 = (const float*)d_in[9];
    const float* Wq   = (const float*)d_in[10];
    const float* Wk   = (const float*)d_in[11];
    const float* bk   = (const float*)d_in[12];
    const float* Wv   = (const float*)d_in[13];
    const float* Wo   = (const float*)d_in[14];
    const float* bo   = (const float*)d_in[15];
    const float* mw0  = (const float*)d_in[16];
    const float* mb0  = (const float*)d_in[17];
    const float* mw1  = (const float*)d_in[18];
    const float* mb1  = (const float*)d_in[19];
    const float* mw2  = (const float*)d_in[20];
    const float* mb2  = (const float*)d_in[21];
    const float* a_w0 = (const float*)d_in[22];
    const float* a_b0 = (const float*)d_in[23];
    const float* a_w1 = (const float*)d_in[24];
    const float* a_b1 = (const float*)d_in[25];
    const float* a_w2 = (const float*)d_in[26];
    const float* a_b2 = (const float*)d_in[27];

    float* cond   = (float*)sym_addr_raw(g_cond);
    float* bufA   = (float*)sym_addr_raw(g_a);
    float* bufB   = (float*)sym_addr_raw(g_b);
    float* h      = (float*)sym_addr_raw(g_h);
    float* t      = (float*)sym_addr_raw(g_t);
    float* q      = (float*)sym_addr_raw(g_q);
    float* k      = (float*)sym_addr_raw(g_k);
    float* v      = (float*)sym_addr_raw(g_v);
    float* params = (float*)sym_addr_raw(g_params);
    float* ld     = (float*)sym_addr_raw(g_ld);
    float* out    = (float*)d_out;

    cudaFuncSetAttribute(gemm_v7_kernel<true , true >,
                         cudaFuncAttributeMaxDynamicSharedMemorySize, GEMM_SMEM);
    cudaFuncSetAttribute(gemm_v7_kernel<false, true >,
                         cudaFuncAttributeMaxDynamicSharedMemorySize, GEMM_SMEM);
    cudaFuncSetAttribute(gemm_v7_kernel<true , false>,
                         cudaFuncAttributeMaxDynamicSharedMemorySize, GEMM_SMEM);
    cudaFuncSetAttribute(gemm_v7_kernel<false, false>,
                         cudaFuncAttributeMaxDynamicSharedMemorySize, GEMM_SMEM);
    cudaFuncSetAttribute(gemm_qkv_kernel,
                         cudaFuncAttributeMaxDynamicSharedMemorySize, GEMM_SMEM);
    cudaFuncSetAttribute(flash_mma_kernel,
                         cudaFuncAttributeMaxDynamicSharedMemorySize, FLASH_SMEM);

    embed_kernel<<<SPAD / 256, 256>>>(pos, scale, press, temp, cond);

    // embedding MLP: 35 -> 512 -> 512 -> 256
    gemm(cond, CONDP, e_w0, e_b0, nullptr, bufA, HID, HID, EMB_IN, CONDP, true);
    gemm(bufA, HID,   e_w1, e_b1, nullptr, bufB, HID, HID, HID, HID, true);
    gemm(bufB, HID,   e_w2, e_b2, nullptr, h,    DIM, DIM, HID, HID, false);

    for (int i = 0; i < NBLK; i++) {
        const float* Wqi = Wq + (size_t)i * DIM * DIM;
        const float* Wki = Wk + (size_t)i * DIM * DIM;
        const float* bki = bk + (size_t)i * DIM;
        const float* Wvi = Wv + (size_t)i * DIM * DIM;
        const float* Woi = Wo + (size_t)i * DIM * DIM;
        const float* boi = bo + (size_t)i * DIM;
        const float* mw0i = mw0 + (size_t)i * HID * DIM;
        const float* mb0i = mb0 + (size_t)i * HID;
        const float* mw1i = mw1 + (size_t)i * HID * HID;
        const float* mb1i = mb1 + (size_t)i * HID;
        const float* mw2i = mw2 + (size_t)i * DIM * HID;
        const float* mb2i = mb2 + (size_t)i * DIM;

        dim3 qkvgrid(DIM / 64, SPAD / 64, 3);
        gemm_qkv_kernel<<<qkvgrid, 256, GEMM_SMEM>>>(h, Wqi, Wki, Wvi, bki,
                                                     q, k, v);

        dim3 fgrid((S_ROWS + 63) / 64, NHEAD, KVSPLIT);
        flash_mma_kernel<<<fgrid, 128, FLASH_SMEM>>>(q, k, v);
        flash_combine_kernel<<<SPAD * DIM / 256, 256>>>(t);

        gemm(t, DIM, Woi, boi, h, h, DIM, DIM, DIM, DIM, false);

        gemm(h,    DIM, mw0i, mb0i, nullptr, bufA, HID, HID, DIM, DIM, true);
        gemm(bufA, HID, mw1i, mb1i, nullptr, bufB, HID, HID, HID, HID, true);
        gemm(bufB, HID, mw2i, mb2i, h,       h,    DIM, DIM, HID, HID, false);
    }

    // affine head: 256 -> 512 -> 512 -> 49
    gemm(h,    DIM, a_w0, a_b0, nullptr, bufA,   HID,     HID, DIM, DIM, true);
    gemm(bufA, HID, a_w1, a_b1, nullptr, bufB,   HID,     HID, HID, HID, true);
    gemm(bufB, HID, a_w2, a_b2, nullptr, params, AFF_OUT, 64,  HID, HID, false);

    int ncopy = out_size < POS_ELEMS ? out_size : POS_ELEMS;
    copy_pos_kernel<<<(ncopy + 255) / 256, 256>>>(pos, out, ncopy);
    spline_kernel<<<(S_ROWS + 255) / 256, 256>>>(pos, params, out, ld);
    reduce_kernel<<<1, 256>>>(ld, out, out_size);
}

// round 10
// speedup vs baseline: 1.2467x; 1.0453x over previous
#include <cuda_runtime.h>
#include <cstdint>
#include <math.h>

// ---------------- problem constants ----------------
#define S_ROWS 2047          // N_PART - 1
#define SPAD   2048
#define DIM    256
#define HID    512
#define NB     16
#define NFREQ  8
#define NBLK   4
#define NHEAD  8
#define EMB_IN 35
#define CONDP  64            // padded cond width
#define AFF_OUT 49
#define POS_ELEMS (2048*3)
#define KVSPLIT 2

// gemm smem: As[2][64][36] + Bs[2][64][36] uint2
#define GEMM_SMEM ((2*64*36 + 2*64*36) * 8)
// flash smem: Ks[2][64][36] + Vs[2][64][36] uint2
#define FLASH_SMEM ((2*64*36 + 2*64*36) * 8)

// ---------------- scratch (static device memory; zero-initialized) --------
__device__ float g_cond[SPAD * CONDP];
__device__ float g_a[SPAD * HID];
__device__ float g_b[SPAD * HID];
__device__ float g_h[SPAD * DIM];
__device__ float g_t[SPAD * DIM];
__device__ float g_q[SPAD * DIM];
__device__ float g_k[SPAD * DIM];
__device__ float g_v[SPAD * DIM];
__device__ float g_po[KVSPLIT][SPAD * DIM];
__device__ float2 g_pml[KVSPLIT][SPAD * NHEAD];
__device__ float g_params[SPAD * AFF_OUT];
__device__ float g_ld[S_ROWS];

// ---------------- helpers ---------------------------------------------------
__device__ __forceinline__ uint32_t f2tf32(float f) {
    uint32_t u;
    asm("cvt.rna.tf32.f32 %0, %1;" : "=r"(u) : "f"(f));
    return u;
}

__device__ __forceinline__ uint2 split_tf32(float f) {
    uint32_t hi = f2tf32(f);
    uint32_t lo = f2tf32(f - __uint_as_float(hi));
    return make_uint2(hi, lo);
}

__device__ __forceinline__ void mma_tf32(float c[4], const uint32_t a[4],
                                         const uint32_t b[2]) {
    asm volatile(
        "mma.sync.aligned.m16n8k8.row.col.f32.tf32.tf32.f32 "
        "{%0,%1,%2,%3}, {%4,%5,%6,%7}, {%8,%9}, {%0,%1,%2,%3};"
        : "+f"(c[0]), "+f"(c[1]), "+f"(c[2]), "+f"(c[3])
        : "r"(a[0]), "r"(a[1]), "r"(a[2]), "r"(a[3]), "r"(b[0]), "r"(b[1]));
}

__device__ __forceinline__ void mma3(float c[4], const uint32_t aH[4],
                                     const uint32_t aL[4], const uint32_t bH[2],
                                     const uint32_t bL[2]) {
    mma_tf32(c, aL, bH);
    mma_tf32(c, aH, bL);
    mma_tf32(c, aH, bH);
}

// ---------------- circular features (padded cond) ----------------------------
__global__ void embed_kernel(const float* __restrict__ pos,
                             const float* __restrict__ scale,
                             const float* __restrict__ press,
                             const float* __restrict__ temp,
                             float* __restrict__ cond) {
    int s = blockIdx.x * blockDim.x + threadIdx.x;
    if (s >= SPAD) return;
    float* c = cond + s * CONDP;
    if (s >= S_ROWS) {
        #pragma unroll
        for (int i = 0; i < CONDP; i++) c[i] = 0.f;
        return;
    }
    const float TWO_PI = 6.28318530717958647692f;
    float xs[2];
    xs[0] = pos[(s + 1) * 3 + 0];
    xs[1] = pos[(s + 1) * 3 + 1];
    #pragma unroll
    for (int cc = 0; cc < 2; cc++) {
        float x = xs[cc];
        #pragma unroll
        for (int f = 1; f <= NFREQ; f++) {
            float sn, cs;
            sincosf(TWO_PI * (float)f * x, &sn, &cs);
            c[cc * 16 + (f - 1)]     = cs;
            c[cc * 16 + 8 + (f - 1)] = sn;
        }
    }
    c[32] = *scale;
    c[33] = *temp;
    c[34] = *press;
    #pragma unroll
    for (int i = EMB_IN; i < CONDP; i++) c[i] = 0.f;
}

// ---------------- GEMM v7: 64x64 tile, double-buffered, prefetch -------------
#define GAS(b,r,c) sm[((b)*64 + (r))*36 + (c)]
#define GBS(b,r,c) sm[4608 + ((b)*64 + (r))*36 + (c)]

template <bool RELU, bool FULL>
__device__ __forceinline__
void gemm_core(const float* __restrict__ A, int lda,
               const float* __restrict__ W,
               const float* __restrict__ bias, const float* __restrict__ res,
               float* __restrict__ C, int Nstore, int Kreal, int Kp) {
    extern __shared__ uint2 sm[];

    const int tid  = threadIdx.x;
    const int lane = tid & 31;
    const int wid  = tid >> 5;
    const int warp_m = wid >> 2;
    const int warp_n = wid & 3;
    const int g   = lane >> 2;
    const int tig = lane & 3;

    const int m0 = blockIdx.y * 64;
    const int n0 = blockIdx.x * 64;

    int ldRow[2], ldCol[2];
    #pragma unroll
    for (int i = 0; i < 2; i++) {
        int f4 = i * 256 + tid;
        ldRow[i] = f4 >> 3;
        ldCol[i] = (f4 & 7) * 4;
    }
    const int stages = Kp >> 5;

    float av[2][4], bv[2][4];

    {
        #pragma unroll
        for (int i = 0; i < 2; i++) {
            float4 a4 = *(const float4*)(A + (size_t)(m0 + ldRow[i]) * lda + ldCol[i]);
            av[i][0] = a4.x; av[i][1] = a4.y; av[i][2] = a4.z; av[i][3] = a4.w;
            if (FULL) {
                float4 w4 = *(const float4*)(W + (size_t)(n0 + ldRow[i]) * Kreal + ldCol[i]);
                bv[i][0] = w4.x; bv[i][1] = w4.y; bv[i][2] = w4.z; bv[i][3] = w4.w;
            } else {
                int n = n0 + ldRow[i];
                #pragma unroll
                for (int j = 0; j < 4; j++) {
                    int kk = ldCol[i] + j;
                    bv[i][j] = (n < Nstore && kk < Kreal)
                             ? W[(size_t)n * Kreal + kk] : 0.f;
                }
            }
        }
        #pragma unroll
        for (int i = 0; i < 2; i++)
            #pragma unroll
            for (int j = 0; j < 4; j++) {
                GAS(0, ldRow[i], ldCol[i] + j) = split_tf32(av[i][j]);
                GBS(0, ldRow[i], ldCol[i] + j) = split_tf32(bv[i][j]);
            }
    }
    __syncthreads();

    float acc[2][2][4];
    #pragma unroll
    for (int mt = 0; mt < 2; mt++)
        #pragma unroll
        for (int nt = 0; nt < 2; nt++)
            #pragma unroll
            for (int i = 0; i < 4; i++) acc[mt][nt][i] = 0.f;

    for (int s = 0; s < stages; s++) {
        const int cur = s & 1;

        if (s + 1 < stages) {
            const int k0 = (s + 1) * 32;
            #pragma unroll
            for (int i = 0; i < 2; i++) {
                float4 a4 = *(const float4*)(A + (size_t)(m0 + ldRow[i]) * lda + k0 + ldCol[i]);
                av[i][0] = a4.x; av[i][1] = a4.y; av[i][2] = a4.z; av[i][3] = a4.w;
                if (FULL) {
                    float4 w4 = *(const float4*)(W + (size_t)(n0 + ldRow[i]) * Kreal + k0 + ldCol[i]);
                    bv[i][0] = w4.x; bv[i][1] = w4.y; bv[i][2] = w4.z; bv[i][3] = w4.w;
                } else {
                    int n = n0 + ldRow[i];
                    #pragma unroll
                    for (int j = 0; j < 4; j++) {
                        int kk = k0 + ldCol[i] + j;
                        bv[i][j] = (n < Nstore && kk < Kreal)
                                 ? W[(size_t)n * Kreal + kk] : 0.f;
                    }
                }
            }
        }

        #pragma unroll
        for (int k8 = 0; k8 < 4; k8++) {
            const int kk = k8 * 8;
            uint32_t aH[2][4], aL[2][4];
            #pragma unroll
            for (int mt = 0; mt < 2; mt++) {
                const int r = warp_m * 32 + mt * 16 + g;
                uint2 p0 = GAS(cur, r,     kk + tig);
                uint2 p1 = GAS(cur, r + 8, kk + tig);
                uint2 p2 = GAS(cur, r,     kk + tig + 4);
                uint2 p3 = GAS(cur, r + 8, kk + tig + 4);
                aH[mt][0] = p0.x; aH[mt][1] = p1.x; aH[mt][2] = p2.x; aH[mt][3] = p3.x;
                aL[mt][0] = p0.y; aL[mt][1] = p1.y; aL[mt][2] = p2.y; aL[mt][3] = p3.y;
            }
            uint32_t bH[2][2], bL[2][2];
            #pragma unroll
            for (int nt = 0; nt < 2; nt++) {
                int ci = warp_n * 16 + nt * 8 + g;
                uint2 q0 = GBS(cur, ci, kk + tig);
                uint2 q1 = GBS(cur, ci, kk + tig + 4);
                bH[nt][0] = q0.x; bH[nt][1] = q1.x;
                bL[nt][0] = q0.y; bL[nt][1] = q1.y;
            }
            #pragma unroll
            for (int mt = 0; mt < 2; mt++)
                #pragma unroll
                for (int nt = 0; nt < 2; nt++)
                    mma3(acc[mt][nt], aH[mt], aL[mt], bH[nt], bL[nt]);
        }

        if (s + 1 < stages) {
            const int nb = (s + 1) & 1;
            #pragma unroll
            for (int i = 0; i < 2; i++)
                #pragma unroll
                for (int j = 0; j < 4; j++) {
                    GAS(nb, ldRow[i], ldCol[i] + j) = split_tf32(av[i][j]);
                    GBS(nb, ldRow[i], ldCol[i] + j) = split_tf32(bv[i][j]);
                }
        }
        __syncthreads();
    }

    #pragma unroll
    for (int mt = 0; mt < 2; mt++) {
        #pragma unroll
        for (int nt = 0; nt < 2; nt++) {
            int r0 = m0 + warp_m * 32 + mt * 16 + g;
            int cb = n0 + warp_n * 16 + nt * 8 + tig * 2;
            #pragma unroll
            for (int half = 0; half < 2; half++) {
                int r = r0 + half * 8;
                if (r >= S_ROWS) continue;
                #pragma unroll
                for (int j = 0; j < 2; j++) {
                    int n = cb + j;
                    if (n >= Nstore) continue;
                    float v = acc[mt][nt][half * 2 + j];
                    if (bias) v += bias[n];
                    if (res)  v += res[(size_t)r * Nstore + n];
                    if (RELU) v = fmaxf(v, 0.f);
                    C[(size_t)r * Nstore + n] = v;
                }
            }
        }
    }
}

template <bool RELU, bool FULL>
__global__ __launch_bounds__(256)
void gemm_v7_kernel(const float* __restrict__ A, int lda,
                    const float* __restrict__ W,
                    const float* __restrict__ bias, const float* __restrict__ res,
                    float* __restrict__ C, int Nstore, int Kreal, int Kp) {
    gemm_core<RELU, FULL>(A, lda, W, bias, res, C, Nstore, Kreal, Kp);
}

// fused q/k/v projection via blockIdx.z
__global__ __launch_bounds__(256)
void gemm_qkv_kernel(const float* __restrict__ h,
                     const float* __restrict__ Wq, const float* __restrict__ Wk,
                     const float* __restrict__ Wv, const float* __restrict__ bk,
                     float* __restrict__ q, float* __restrict__ k,
                     float* __restrict__ v) {
    int z = blockIdx.z;
    const float* W = (z == 0) ? Wq : (z == 1) ? Wk : Wv;
    const float* bias = (z == 1) ? bk : nullptr;
    float* C = (z == 0) ? q : (z == 1) ? k : v;
    gemm_core<false, true>(h, DIM, W, bias, nullptr, C, DIM, DIM, DIM);
}

// ---------------- flash attention v6: 128 q-rows / block (8 warps) ----------
#define FKS(b,r,c) sm[((b)*64 + (r))*36 + (c)]
#define FVS(b,r,c) sm[4608 + ((b)*64 + (r))*36 + (c)]

__global__ __launch_bounds__(256)
void flash_mma_kernel(const float* __restrict__ q,
                      const float* __restrict__ k,
                      const float* __restrict__ v) {
    extern __shared__ uint2 sm[];

    const int S = S_ROWS, D = DIM;
    const int head = blockIdx.y;
    const int z = blockIdx.z;
    const int s0 = blockIdx.x * 128;
    const int tid = threadIdx.x;
    const int lane = tid & 31;
    const int wid = tid >> 5;          // 0..7, each warp = 16 q rows
    const int g = lane >> 2;
    const int tig = lane & 3;
    const float scl = 0.17677669529663688f;
    const int TPB = 32 / KVSPLIT;
    const int tbase = z * TPB;

    // Q fragments from padded global (scale folded)
    uint32_t aQH[4][4], aQL[4][4];
    {
        const int ra = s0 + wid * 16 + g;
        const int rb = ra + 8;
        #pragma unroll
        for (int k8 = 0; k8 < 4; k8++) {
            const int c0 = head * 32 + k8 * 8 + tig;
            uint2 p0 = split_tf32(q[(size_t)ra * D + c0] * scl);
            uint2 p1 = split_tf32(q[(size_t)rb * D + c0] * scl);
            uint2 p2 = split_tf32(q[(size_t)ra * D + c0 + 4] * scl);
            uint2 p3 = split_tf32(q[(size_t)rb * D + c0 + 4] * scl);
            aQH[k8][0] = p0.x; aQH[k8][1] = p1.x; aQH[k8][2] = p2.x; aQH[k8][3] = p3.x;
            aQL[k8][0] = p0.y; aQL[k8][1] = p1.y; aQL[k8][2] = p2.y; aQL[k8][3] = p3.y;
        }
    }

    // K/V tile load: 2 float4 per thread per operand (256 threads, 64x32)
    float4 kr[2], vr[2];
    int ldR[2], ldC[2];
    #pragma unroll
    for (int i = 0; i < 2; i++) {
        int cc = i * 256 + tid;        // 0..511
        ldR[i] = cc >> 3;              // 0..63
        ldC[i] = (cc & 7) * 4;
    }

    #pragma unroll
    for (int i = 0; i < 2; i++) {
        size_t off = (size_t)(tbase * 64 + ldR[i]) * D + head * 32 + ldC[i];
        kr[i] = *(const float4*)&k[off];
        vr[i] = *(const float4*)&v[off];
    }
    #pragma unroll
    for (int i = 0; i < 2; i++) {
        FKS(0, ldR[i], ldC[i] + 0) = split_tf32(kr[i].x);
        FKS(0, ldR[i], ldC[i] + 1) = split_tf32(kr[i].y);
        FKS(0, ldR[i], ldC[i] + 2) = split_tf32(kr[i].z);
        FKS(0, ldR[i], ldC[i] + 3) = split_tf32(kr[i].w);
        FVS(0, ldR[i], ldC[i] + 0) = split_tf32(vr[i].x);
        FVS(0, ldR[i], ldC[i] + 1) = split_tf32(vr[i].y);
        FVS(0, ldR[i], ldC[i] + 2) = split_tf32(vr[i].z);
        FVS(0, ldR[i], ldC[i] + 3) = split_tf32(vr[i].w);
    }
    __syncthreads();

    float co[4][4];
    #pragma unroll
    for (int nt = 0; nt < 4; nt++)
        #pragma unroll
        for (int i = 0; i < 4; i++) co[nt][i] = 0.f;
    float m_a = -INFINITY, m_b = -INFINITY, l_a = 0.f, l_b = 0.f;

    for (int j = 0; j < TPB; j++) {
        const int cur = j & 1;
        const int t0 = (tbase + j) * 64;

        if (j + 1 < TPB) {
            const int t1 = t0 + 64;
            #pragma unroll
            for (int i = 0; i < 2; i++) {
                size_t off = (size_t)(t1 + ldR[i]) * D + head * 32 + ldC[i];
                kr[i] = *(const float4*)&k[off];
                vr[i] = *(const float4*)&v[off];
            }
        }

        // scores: Q(16x32) @ K^T(32x64)
        float cs[8][4];
        #pragma unroll
        for (int nt = 0; nt < 8; nt++)
            #pragma unroll
            for (int i = 0; i < 4; i++) cs[nt][i] = 0.f;

        #pragma unroll
        for (int k8 = 0; k8 < 4; k8++) {
            const int kk = k8 * 8;
            #pragma unroll
            for (int nt = 0; nt < 8; nt++) {
                int ci = nt * 8 + g;
                uint2 q0 = FKS(cur, ci, kk + tig);
                uint2 q1 = FKS(cur, ci, kk + tig + 4);
                uint32_t bH[2] = {q0.x, q1.x};
                uint32_t bL[2] = {q0.y, q1.y};
                mma3(cs[nt], aQH[k8], aQL[k8], bH, bL);
            }
        }

        // mask + online softmax
        float mx_a = m_a, mx_b = m_b;
        #pragma unroll
        for (int nt = 0; nt < 8; nt++) {
            int col0 = t0 + nt * 8 + 2 * tig;
            if (col0 >= S)     { cs[nt][0] = -INFINITY; cs[nt][2] = -INFINITY; }
            if (col0 + 1 >= S) { cs[nt][1] = -INFINITY; cs[nt][3] = -INFINITY; }
            mx_a = fmaxf(mx_a, fmaxf(cs[nt][0], cs[nt][1]));
            mx_b = fmaxf(mx_b, fmaxf(cs[nt][2], cs[nt][3]));
        }
        mx_a = fmaxf(mx_a, __shfl_xor_sync(0xffffffffu, mx_a, 1));
        mx_a = fmaxf(mx_a, __shfl_xor_sync(0xffffffffu, mx_a, 2));
        mx_b = fmaxf(mx_b, __shfl_xor_sync(0xffffffffu, mx_b, 1));
        mx_b = fmaxf(mx_b, __shfl_xor_sync(0xffffffffu, mx_b, 2));
        float corr_a = __expf(m_a - mx_a);
        float corr_b = __expf(m_b - mx_b);
        m_a = mx_a; m_b = mx_b;

        float la = 0.f, lb = 0.f;
        #pragma unroll
        for (int nt = 0; nt < 8; nt++) {
            cs[nt][0] = __expf(cs[nt][0] - m_a);
            cs[nt][1] = __expf(cs[nt][1] - m_a);
            cs[nt][2] = __expf(cs[nt][2] - m_b);
            cs[nt][3] = __expf(cs[nt][3] - m_b);
            la += cs[nt][0] + cs[nt][1];
            lb += cs[nt][2] + cs[nt][3];
        }
        la += __shfl_xor_sync(0xffffffffu, la, 1);
        la += __shfl_xor_sync(0xffffffffu, la, 2);
        lb += __shfl_xor_sync(0xffffffffu, lb, 1);
        lb += __shfl_xor_sync(0xffffffffu, lb, 2);
        l_a = l_a * corr_a + la;
        l_b = l_b * corr_b + lb;

        #pragma unroll
        for (int nt = 0; nt < 4; nt++) {
            co[nt][0] *= corr_a; co[nt][1] *= corr_a;
            co[nt][2] *= corr_b; co[nt][3] *= corr_b;
        }

        // PV: permute score C-frags -> A-frags via quad shuffles
        {
            const int s1 = (lane & ~3) | (tig >> 1);
            const int s2 = s1 + 2;
            const bool odd = (tig & 1) != 0;
            #pragma unroll
            for (int k8v = 0; k8v < 8; k8v++) {
                float q00 = __shfl_sync(0xffffffffu, cs[k8v][0], s1);
                float q01 = __shfl_sync(0xffffffffu, cs[k8v][1], s1);
                float q02 = __shfl_sync(0xffffffffu, cs[k8v][2], s1);
                float q03 = __shfl_sync(0xffffffffu, cs[k8v][3], s1);
                float r00 = __shfl_sync(0xffffffffu, cs[k8v][0], s2);
                float r01 = __shfl_sync(0xffffffffu, cs[k8v][1], s2);
                float r02 = __shfl_sync(0xffffffffu, cs[k8v][2], s2);
                float r03 = __shfl_sync(0xffffffffu, cs[k8v][3], s2);
                float a0 = odd ? q01 : q00;
                float a1 = odd ? q03 : q02;
                float a2 = odd ? r01 : r00;
                float a3 = odd ? r03 : r02;
                uint2 h0 = split_tf32(a0), h1 = split_tf32(a1);
                uint2 h2 = split_tf32(a2), h3 = split_tf32(a3);
                uint32_t aH[4] = {h0.x, h1.x, h2.x, h3.x};
                uint32_t aL[4] = {h0.y, h1.y, h2.y, h3.y};
                const int kkv = k8v * 8;
                #pragma unroll
                for (int nt = 0; nt < 4; nt++) {
                    uint2 q0 = FVS(cur, kkv + tig,     nt * 8 + g);
                    uint2 q1 = FVS(cur, kkv + tig + 4, nt * 8 + g);
                    uint32_t bH[2] = {q0.x, q1.x};
                    uint32_t bL[2] = {q0.y, q1.y};
                    mma3(co[nt], aH, aL, bH, bL);
                }
            }
        }

        if (j + 1 < TPB) {
            const int nb = (j + 1) & 1;
            #pragma unroll
            for (int i = 0; i < 2; i++) {
                FKS(nb, ldR[i], ldC[i] + 0) = split_tf32(kr[i].x);
                FKS(nb, ldR[i], ldC[i] + 1) = split_tf32(kr[i].y);
                FKS(nb, ldR[i], ldC[i] + 2) = split_tf32(kr[i].z);
                FKS(nb, ldR[i], ldC[i] + 3) = split_tf32(kr[i].w);
                FVS(nb, ldR[i], ldC[i] + 0) = split_tf32(vr[i].x);
                FVS(nb, ldR[i], ldC[i] + 1) = split_tf32(vr[i].y);
                FVS(nb, ldR[i], ldC[i] + 2) = split_tf32(vr[i].z);
                FVS(nb, ldR[i], ldC[i] + 3) = split_tf32(vr[i].w);
            }
            __syncthreads();
        }
    }

    float* po = g_po[z];
    int srow_a = s0 + wid * 16 + g;
    int srow_b = srow_a + 8;
    #pragma unroll
    for (int nt = 0; nt < 4; nt++) {
        int col = head * 32 + nt * 8 + 2 * tig;
        if (srow_a < S) {
            float2 w2 = make_float2(co[nt][0], co[nt][1]);
            *(float2*)&po[(size_t)srow_a * D + col] = w2;
        }
        if (srow_b < S) {
            float2 w2 = make_float2(co[nt][2], co[nt][3]);
            *(float2*)&po[(size_t)srow_b * D + col] = w2;
        }
    }
    if (tig == 0) {
        if (srow_a < S) g_pml[z][(size_t)srow_a * NHEAD + head] = make_float2(m_a, l_a);
        if (srow_b < S) g_pml[z][(size_t)srow_b * NHEAD + head] = make_float2(m_b, l_b);
    }
}

// combine kv-split partials -> o
__global__ void flash_combine_kernel(float* __restrict__ o) {
    int idx = blockIdx.x * 256 + threadIdx.x;
    if (idx >= SPAD * DIM) return;
    int row = idx >> 8;
    if (row >= S_ROWS) return;
    int head = (idx & 255) >> 5;
    float2 ml0 = g_pml[0][(size_t)row * NHEAD + head];
    float2 ml1 = g_pml[1][(size_t)row * NHEAD + head];
    float m = fmaxf(ml0.x, ml1.x);
    float e0 = __expf(ml0.x - m);
    float e1 = __expf(ml1.x - m);
    float l = ml0.y * e0 + ml1.y * e1;
    o[idx] = (g_po[0][idx] * e0 + g_po[1][idx] * e1) / l;
}

// ---------------- RQS spline ------------------------------------------------
__device__ __forceinline__ float softplusf(float x) {
    return (x > 20.f) ? x : log1pf(expf(x));
}

__global__ void spline_kernel(const float* __restrict__ pos,
                              const float* __restrict__ params,
                              float* __restrict__ out,
                              float* __restrict__ ld) {
    int s = blockIdx.x * blockDim.x + threadIdx.x;
    if (s >= S_ROWS) return;
    const float* p = params + s * AFF_OUT;
    const float MINB = 1e-4f;
    const float MINS = 1e-4f;

    float x = pos[(s + 1) * 3 + 2];
    bool inside = (x >= 0.f) && (x <= 1.f);
    float xc = fminf(fmaxf(x, 0.f), 1.f);

    float ew[NB], eh[NB];
    float mw = -INFINITY, mh = -INFINITY;
    #pragma unroll
    for (int i = 0; i < NB; i++) { mw = fmaxf(mw, p[i]); mh = fmaxf(mh, p[NB + i]); }
    float sw = 0.f, sh = 0.f;
    #pragma unroll
    for (int i = 0; i < NB; i++) {
        ew[i] = expf(p[i] - mw);        sw += ew[i];
        eh[i] = expf(p[NB + i] - mh);   sh += eh[i];
    }
    float fac = 1.f - NB * MINB;
    float isw = fac / sw, ish = fac / sh;

    float off = logf(expm1f(1.f - MINS));
    float d[NB + 1];
    #pragma unroll
    for (int i = 0; i < NB; i++) d[i] = softplusf(p[2 * NB + i] + off) + MINS;
    d[NB] = d[0];

    float xp[NB + 1], yp[NB + 1];
    xp[0] = 0.f; yp[0] = 0.f;
    #pragma unroll
    for (int i = 0; i < NB; i++) {
        xp[i + 1] = xp[i] + (ew[i] * isw + MINB);
        yp[i + 1] = yp[i] + (eh[i] * ish + MINB);
    }

    int cnt = 0;
    #pragma unroll
    for (int i = 0; i < NB + 1; i++) cnt += (xc >= xp[i]) ? 1 : 0;
    int kb = cnt - 1;
    if (kb < 0) kb = 0;
    if (kb > NB - 1) kb = NB - 1;

    float xk = xp[kb], xk1 = xp[kb + 1];
    float yk = yp[kb], yk1 = yp[kb + 1];
    float dk = d[kb],  dk1 = d[kb + 1];
    float w = xk1 - xk;
    float h = yk1 - yk;
    float sl = h / w;
    float z = (xc - xk) / w;
    float z1 = 1.f - z;
    float den = sl + (dk1 + dk - 2.f * sl) * z * z1;
    float y = yk + h * (sl * z * z + dk * z * z1) / den;
    float logdet = 2.f * logf(sl)
                 + logf(dk1 * z * z + 2.f * sl * z * z1 + dk * z1 * z1)
                 - 2.f * logf(den);

    out[(s + 1) * 3 + 2] = inside ? y : x;
    ld[s] = inside ? logdet : 0.f;
}

// ---------------- output copy + deterministic logdet reduction -------------
__global__ void copy_pos_kernel(const float* __restrict__ pos,
                                float* __restrict__ out, int n) {
    int i = blockIdx.x * blockDim.x + threadIdx.x;
    if (i < n) out[i] = pos[i];
}

__global__ void reduce_kernel(const float* __restrict__ ld,
                              float* __restrict__ out, int out_size) {
    __shared__ float sh[256];
    float s = 0.f;
    for (int i = threadIdx.x; i < S_ROWS; i += 256) s += ld[i];
    sh[threadIdx.x] = s;
    __syncthreads();
    for (int st = 128; st > 0; st >>= 1) {
        if (threadIdx.x < st) sh[threadIdx.x] += sh[threadIdx.x + st];
        __syncthreads();
    }
    if (threadIdx.x == 0 && out_size > POS_ELEMS) out[POS_ELEMS] = sh[0];
}

// ---------------- host orchestration ---------------------------------------
template <typename T>
static void* sym_addr_raw(T& sym) {
    void* p = nullptr;
    cudaGetSymbolAddress(&p, sym);
    return p;
}

static void gemm(const float* A, int lda, const float* W, const float* bias,
                 const float* res, float* C, int Nstore, int Npad,
                 int Kreal, int Kp, bool relu) {
    dim3 grid(Npad / 64, SPAD / 64);
    bool full = (Nstore % 64 == 0) && (Kreal == Kp);
    if (full) {
        if (relu)
            gemm_v7_kernel<true , true ><<<grid, 256, GEMM_SMEM>>>(A, lda, W, bias, res, C, Nstore, Kreal, Kp);
        else
            gemm_v7_kernel<false, true ><<<grid, 256, GEMM_SMEM>>>(A, lda, W, bias, res, C, Nstore, Kreal, Kp);
    } else {
        if (relu)
            gemm_v7_kernel<true , false><<<grid, 256, GEMM_SMEM>>>(A, lda, W, bias, res, C, Nstore, Kreal, Kp);
        else
            gemm_v7_kernel<false, false><<<grid, 256, GEMM_SMEM>>>(A, lda, W, bias, res, C, Nstore, Kreal, Kp);
    }
}

extern "C" void kernel_launch(void* const* d_in, const int* in_sizes, int n_in,
                              void* d_out, int out_size) {
    const float* pos   = (const float*)d_in[0];
    const float* scale = (const float*)d_in[1];
    const float* press = (const float*)d_in[2];
    const float* temp  = (const float*)d_in[3];
    const float* e_w0 = (const float*)d_in[4];
    const float* e_b0 = (const float*)d_in[5];
    const float* e_w1 = (const float*)d_in[6];
    const float* e_b1 = (const float*)d_in[7];
    const float* e_w2 = (const float*)d_in[8];
    const float* e_b2 = (const float*)d_in[9];
    const float* Wq   = (const float*)d_in[10];
    const float* Wk   = (const float*)d_in[11];
    const float* bk   = (const float*)d_in[12];
    const float* Wv   = (const float*)d_in[13];
    const float* Wo   = (const float*)d_in[14];
    const float* bo   = (const float*)d_in[15];
    const float* mw0  = (const float*)d_in[16];
    const float* mb0  = (const float*)d_in[17];
    const float* mw1  = (const float*)d_in[18];
    const float* mb1  = (const float*)d_in[19];
    const float* mw2  = (const float*)d_in[20];
    const float* mb2  = (const float*)d_in[21];
    const float* a_w0 = (const float*)d_in[22];
    const float* a_b0 = (const float*)d_in[23];
    const float* a_w1 = (const float*)d_in[24];
    const float* a_b1 = (const float*)d_in[25];
    const float* a_w2 = (const float*)d_in[26];
    const float* a_b2 = (const float*)d_in[27];

    float* cond   = (float*)sym_addr_raw(g_cond);
    float* bufA   = (float*)sym_addr_raw(g_a);
    float* bufB   = (float*)sym_addr_raw(g_b);
    float* h      = (float*)sym_addr_raw(g_h);
    float* t      = (float*)sym_addr_raw(g_t);
    float* q      = (float*)sym_addr_raw(g_q);
    float* k      = (float*)sym_addr_raw(g_k);
    float* v      = (float*)sym_addr_raw(g_v);
    float* params = (float*)sym_addr_raw(g_params);
    float* ld     = (float*)sym_addr_raw(g_ld);
    float* out    = (float*)d_out;

    cudaFuncSetAttribute(gemm_v7_kernel<true , true >,
                         cudaFuncAttributeMaxDynamicSharedMemorySize, GEMM_SMEM);
    cudaFuncSetAttribute(gemm_v7_kernel<false, true >,
                         cudaFuncAttributeMaxDynamicSharedMemorySize, GEMM_SMEM);
    cudaFuncSetAttribute(gemm_v7_kernel<true , false>,
                         cudaFuncAttributeMaxDynamicSharedMemorySize, GEMM_SMEM);
    cudaFuncSetAttribute(gemm_v7_kernel<false, false>,
                         cudaFuncAttributeMaxDynamicSharedMemorySize, GEMM_SMEM);
    cudaFuncSetAttribute(gemm_qkv_kernel,
                         cudaFuncAttributeMaxDynamicSharedMemorySize, GEMM_SMEM);
    cudaFuncSetAttribute(flash_mma_kernel,
                         cudaFuncAttributeMaxDynamicSharedMemorySize, FLASH_SMEM);

    embed_kernel<<<SPAD / 256, 256>>>(pos, scale, press, temp, cond);

    // embedding MLP: 35 -> 512 -> 512 -> 256
    gemm(cond, CONDP, e_w0, e_b0, nullptr, bufA, HID, HID, EMB_IN, CONDP, true);
    gemm(bufA, HID,   e_w1, e_b1, nullptr, bufB, HID, HID, HID, HID, true);
    gemm(bufB, HID,   e_w2, e_b2, nullptr, h,    DIM, DIM, HID, HID, false);

    for (int i = 0; i < NBLK; i++) {
        const float* Wqi = Wq + (size_t)i * DIM * DIM;
        const float* Wki = Wk + (size_t)i * DIM * DIM;
        const float* bki = bk + (size_t)i * DIM;
        const float* Wvi = Wv + (size_t)i * DIM * DIM;
        const float* Woi = Wo + (size_t)i * DIM * DIM;
        const float* boi = bo + (size_t)i * DIM;
        const float* mw0i = mw0 + (size_t)i * HID * DIM;
        const float* mb0i = mb0 + (size_t)i * HID;
        const float* mw1i = mw1 + (size_t)i * HID * HID;
        const float* mb1i = mb1 + (size_t)i * HID;
        const float* mw2i = mw2 + (size_t)i * DIM * HID;
        const float* mb2i = mb2 + (size_t)i * DIM;

        dim3 qkvgrid(DIM / 64, SPAD / 64, 3);
        gemm_qkv_kernel<<<qkvgrid, 256, GEMM_SMEM>>>(h, Wqi, Wki, Wvi, bki,
                                                     q, k, v);

        dim3 fgrid(SPAD / 128, NHEAD, KVSPLIT);
        flash_mma_kernel<<<fgrid, 256, FLASH_SMEM>>>(q, k, v);
        flash_combine_kernel<<<SPAD * DIM / 256, 256>>>(t);

        gemm(t, DIM, Woi, boi, h, h, DIM, DIM, DIM, DIM, false);

        gemm(h,    DIM, mw0i, mb0i, nullptr, bufA, HID, HID, DIM, DIM, true);
        gemm(bufA, HID, mw1i, mb1i, nullptr, bufB, HID, HID, HID, HID, true);
        gemm(bufB, HID, mw2i, mb2i, h,       h,    DIM, DIM, HID, HID, false);
    }

    // affine head: 256 -> 512 -> 512 -> 49
    gemm(h,    DIM, a_w0, a_b0, nullptr, bufA,   HID,     HID, DIM, DIM, true);
    gemm(bufA, HID, a_w1, a_b1, nullptr, bufB,   HID,     HID, HID, HID, true);
    gemm(bufB, HID, a_w2, a_b2, nullptr, params, AFF_OUT, 64,  HID, HID, false);

    int ncopy = out_size < POS_ELEMS ? out_size : POS_ELEMS;
    copy_pos_kernel<<<(ncopy + 255) / 256, 256>>>(pos, out, ncopy);
    spline_kernel<<<(S_ROWS + 255) / 256, 256>>>(pos, params, out, ld);
    reduce_kernel<<<1, 256>>>(ld, out, out_size);
}